// round 5
// baseline (speedup 1.0000x reference)
#include <cuda_runtime.h>
#include <cuda_bf16.h>
#include <math.h>
#include <stdint.h>

#define BATCH 4
#define SEQ   4096
#define DIM   1024
#define MROWS (BATCH*SEQ)       // 16384
#define KSTORE 2048             // [hi | lo] per row, bf16
#define NCH   256
#define CROWS (SEQ / NCH)       // 16

// ---- mma.sync GEMM tiling ----
#define BM 128
#define BN 256
#define KITERS 48               // 3072 effective K (3-term split)
#define STAGES 3
#define A_ST (BM * 128)         // 16384 B
#define B_ST (BN * 128)         // 32768 B
#define STAGE_B (A_ST + B_ST)   // 49152
#define SMEM_DYN (STAGES * STAGE_B)   // 147456

// -------- scratch (static device globals; no runtime allocation) -----------
__device__ __nv_bfloat16 g_xe[(size_t)MROWS * KSTORE];   // 64MB  [row][ah|al]
__device__ __nv_bfloat16 g_we[4][(size_t)DIM * KSTORE];  // 16MB
__device__ float  g_q[(size_t)MROWS * DIM];
__device__ float  g_k[(size_t)MROWS * DIM];
__device__ float  g_v[(size_t)MROWS * DIM];
__device__ float  g_r[(size_t)MROWS * DIM];
__device__ float2 g_part[BATCH * NCH * DIM];
__device__ float2 g_Fs[BATCH * DIM];

// ============================================================================
// helpers
// ============================================================================
__device__ __forceinline__ uint32_t smem_u32(const void* p) {
    uint32_t a;
    asm("{ .reg .u64 t; cvta.to.shared.u64 t, %1; cvt.u32.u64 %0, t; }" : "=r"(a) : "l"(p));
    return a;
}

__device__ __forceinline__ void cp16(uint32_t dst, const void* src) {
    asm volatile("cp.async.cg.shared.global [%0], [%1], 16;" :: "r"(dst), "l"(src) : "memory");
}
#define CP_COMMIT() asm volatile("cp.async.commit_group;" ::: "memory")
#define CP_WAIT1()  asm volatile("cp.async.wait_group 1;" ::: "memory")

__device__ __forceinline__ void ldmx4(uint32_t& r0, uint32_t& r1, uint32_t& r2, uint32_t& r3,
                                      uint32_t addr) {
    asm volatile("ldmatrix.sync.aligned.m8n8.x4.shared.b16 {%0,%1,%2,%3}, [%4];"
                 : "=r"(r0), "=r"(r1), "=r"(r2), "=r"(r3) : "r"(addr));
}

__device__ __forceinline__ void mma16816(float* c, uint32_t a0, uint32_t a1, uint32_t a2,
                                         uint32_t a3, uint32_t b0, uint32_t b1) {
    asm volatile(
        "mma.sync.aligned.m16n8k16.row.col.f32.bf16.bf16.f32 "
        "{%0,%1,%2,%3}, {%4,%5,%6,%7}, {%8,%9}, {%0,%1,%2,%3};"
        : "+f"(c[0]), "+f"(c[1]), "+f"(c[2]), "+f"(c[3])
        : "r"(a0), "r"(a1), "r"(a2), "r"(a3), "r"(b0), "r"(b1));
}

__device__ __forceinline__ float tanh_fast(float x) {
    float ax = fabsf(x);
    float e = __expf(-2.0f * ax);
    float t = __fdividef(1.0f - e, 1.0f + e);
    return copysignf(t, x);
}

// swizzled smem byte offset within a (rows x 128B) tile
__device__ __forceinline__ uint32_t swz(uint32_t row, uint32_t cg) {
    return row * 128u + ((cg ^ (row & 7u)) << 4);
}

// ============================================================================
// Conversion: fp32 -> hi/lo bf16 halves  (row-major, [hi(1024) | lo(1024)])
// ============================================================================
__global__ void __launch_bounds__(256) convert_x_kernel(const float* __restrict__ x)
{
    const size_t idx = (size_t)blockIdx.x * 256 + threadIdx.x;
    const size_t row = idx >> 10, d = idx & 1023;
    float v = x[idx];
    __nv_bfloat16 hi = __float2bfloat16(v);
    __nv_bfloat16 lo = __float2bfloat16(v - __bfloat162float(hi));
    g_xe[row * KSTORE + d]        = hi;
    g_xe[row * KSTORE + 1024 + d] = lo;
}

__global__ void __launch_bounds__(256) convert_w_kernel(
    const float* __restrict__ Wq, const float* __restrict__ Wk,
    const float* __restrict__ Wv, const float* __restrict__ Wr)
{
    const int w = blockIdx.y;
    const float* W = (w == 0) ? Wq : (w == 1) ? Wk : (w == 2) ? Wv : Wr;
    const size_t idx = (size_t)blockIdx.x * 256 + threadIdx.x;
    const size_t row = idx >> 10, d = idx & 1023;
    float v = W[idx];
    __nv_bfloat16 hi = __float2bfloat16(v);
    __nv_bfloat16 lo = __float2bfloat16(v - __bfloat162float(hi));
    g_we[w][row * KSTORE + d]        = hi;
    g_we[w][row * KSTORE + 1024 + d] = lo;
}

// ============================================================================
// bf16 mma.sync GEMM, 3-term split, BM=128 x BN=256, 16 warps (warp 64x32)
// ============================================================================
__global__ void __launch_bounds__(512, 1) gemm_mma_kernel(
    const float* __restrict__ bq, const float* __restrict__ bk,
    const float* __restrict__ bv, const float* __restrict__ br)
{
    extern __shared__ char dsm[];
    const uint32_t smem = smem_u32(dsm);

    const int tid = threadIdx.x, wid = tid >> 5, lane = tid & 31;
    const int nb = blockIdx.x, mb = blockIdx.y, sel = blockIdx.z;
    const int wm = wid & 1, wn = wid >> 1;       // warp tile 64(m) x 32(n)
    const float* bias = (sel == 0) ? bq : (sel == 1) ? bk : (sel == 2) ? bv : br;
    float* C = (sel == 0) ? g_q : (sel == 1) ? g_k : (sel == 2) ? g_v : g_r;

    const char* a_base = (const char*)g_xe + (size_t)mb * BM * 4096;
    const char* b_base = (const char*)g_we[sel] + (size_t)nb * BN * 4096;

    const uint32_t crow0 = (uint32_t)(tid >> 3);   // 0..63
    const uint32_t ccg = (uint32_t)(tid & 7);

    float acc[4][4][4];
#pragma unroll
    for (int i = 0; i < 4; i++)
#pragma unroll
        for (int j = 0; j < 4; j++)
#pragma unroll
            for (int q = 0; q < 4; q++) acc[i][j][q] = 0.f;

    auto issue = [&](int stage, int kc) {
        const int akc = (kc < 32) ? kc : kc - 32;
        const int bkc = (kc < 16) ? kc : kc - 16;
        const uint32_t sA = smem + stage * STAGE_B;
        const uint32_t sB = sA + A_ST;
#pragma unroll
        for (int j = 0; j < 2; j++) {
            const uint32_t r = crow0 + 64u * j;
            cp16(sA + swz(r, ccg), a_base + (size_t)r * 4096 + akc * 128 + ccg * 16);
        }
#pragma unroll
        for (int j = 0; j < 4; j++) {
            const uint32_t r = crow0 + 64u * j;
            cp16(sB + swz(r, ccg), b_base + (size_t)r * 4096 + bkc * 128 + ccg * 16);
        }
    };

    issue(0, 0); CP_COMMIT();
    issue(1, 1); CP_COMMIT();

    const uint32_t a_row = (uint32_t)(wm * 64 + (lane & 15));
    const uint32_t a_kg  = (uint32_t)(lane >> 4);
    const uint32_t b_row = (uint32_t)(wn * 32 + (lane & 7) + ((lane >> 4) << 3));
    const uint32_t b_kg  = (uint32_t)((lane >> 3) & 1);

    for (int kc = 0; kc < KITERS; kc++) {
        const int s = kc % STAGES;
        CP_WAIT1();
        __syncthreads();
        const uint32_t sA = smem + s * STAGE_B;
        const uint32_t sB = sA + A_ST;
#pragma unroll
        for (int ks = 0; ks < 4; ks++) {
            uint32_t a[4][4];
#pragma unroll
            for (int mf = 0; mf < 4; mf++)
                ldmx4(a[mf][0], a[mf][1], a[mf][2], a[mf][3],
                      sA + swz(a_row + mf * 16, a_kg + ks * 2));
            uint32_t b[2][4];
#pragma unroll
            for (int nf2 = 0; nf2 < 2; nf2++)
                ldmx4(b[nf2][0], b[nf2][1], b[nf2][2], b[nf2][3],
                      sB + swz(b_row + nf2 * 16, b_kg + ks * 2));
#pragma unroll
            for (int mf = 0; mf < 4; mf++) {
#pragma unroll
                for (int nf2 = 0; nf2 < 2; nf2++) {
                    mma16816(acc[mf][nf2 * 2 + 0], a[mf][0], a[mf][1], a[mf][2], a[mf][3],
                             b[nf2][0], b[nf2][1]);
                    mma16816(acc[mf][nf2 * 2 + 1], a[mf][0], a[mf][1], a[mf][2], a[mf][3],
                             b[nf2][2], b[nf2][3]);
                }
            }
        }
        if (kc + 2 < KITERS) issue((kc + 2) % STAGES, kc + 2);
        CP_COMMIT();
    }

    // epilogue: bias + tanh + fp32 store
#pragma unroll
    for (int mf = 0; mf < 4; mf++) {
        const int r0 = mb * BM + wm * 64 + mf * 16 + (lane >> 2);
        const int r1 = r0 + 8;
#pragma unroll
        for (int nf = 0; nf < 4; nf++) {
            const int col = nb * BN + wn * 32 + nf * 8 + (lane & 3) * 2;
            const float2 b2 = *(const float2*)(bias + col);
            float2 o0, o1;
            o0.x = tanh_fast(acc[mf][nf][0] + b2.x);
            o0.y = tanh_fast(acc[mf][nf][1] + b2.y);
            o1.x = tanh_fast(acc[mf][nf][2] + b2.x);
            o1.y = tanh_fast(acc[mf][nf][3] + b2.y);
            *(float2*)(C + (size_t)r0 * DIM + col) = o0;
            *(float2*)(C + (size_t)r1 * DIM + col) = o1;
        }
    }
}

// ============================================================================
// Radix-4 Stockham FFT, N=1024, 256 threads, 5 stages.
// Separate re/im float arrays with +1-per-32 skew for bank-conflict avoidance.
// twr/twi[e] = exp(-2*pi*i*e/1024), e in [0,256). inv=1: conjugate (no scale).
// After 5 stages (odd), result lives in the arrays passed as (br,bi).
// ============================================================================
#define SK(i) ((i) + ((i) >> 5))
#define FBUF 1056                 // 1024 + 32 skew

__device__ __forceinline__ void fft_stage(
    const float* __restrict__ ar, const float* __restrict__ ai,
    float* __restrict__ br, float* __restrict__ bi,
    const float* __restrict__ twr, const float* __restrict__ twi,
    int t, int m, int inv)
{
    const int k = t & (m - 1);
    const int jm = t - k;
    const float x0r = ar[SK(t)],       x0i = ai[SK(t)];
    const float x1r = ar[SK(t + 256)], x1i = ai[SK(t + 256)];
    const float x2r = ar[SK(t + 512)], x2i = ai[SK(t + 512)];
    const float x3r = ar[SK(t + 768)], x3i = ai[SK(t + 768)];
    const float t0r = x0r + x2r, t0i = x0i + x2i;
    const float t1r = x1r + x3r, t1i = x1i + x3i;
    const float t2r = x0r - x2r, t2i = x0i - x2i;
    const float dr  = x1r - x3r, di  = x1i - x3i;
    float t3r, t3i;
    if (inv) { t3r = -di; t3i = dr; } else { t3r = di; t3i = -dr; }
    float w1r = twr[jm], w1i = twi[jm];
    if (inv) w1i = -w1i;
    const float w2r = fmaf(w1r, w1r, -w1i * w1i), w2i = 2.0f * w1r * w1i;
    const float w3r = fmaf(w2r, w1r, -w2i * w1i), w3i = fmaf(w2r, w1i, w2i * w1r);
    const int o = 4 * jm + k;
    br[SK(o)] = t0r + t1r;  bi[SK(o)] = t0i + t1i;
    const float ur = t2r + t3r, ui = t2i + t3i;
    br[SK(o + m)] = fmaf(w1r, ur, -w1i * ui);  bi[SK(o + m)] = fmaf(w1r, ui, w1i * ur);
    const float vr = t0r - t1r, vi = t0i - t1i;
    br[SK(o + 2 * m)] = fmaf(w2r, vr, -w2i * vi);  bi[SK(o + 2 * m)] = fmaf(w2r, vi, w2i * vr);
    const float sr = t2r - t3r, si = t2i - t3i;
    br[SK(o + 3 * m)] = fmaf(w3r, sr, -w3i * si);  bi[SK(o + 3 * m)] = fmaf(w3r, si, w3i * sr);
}

// 5 radix-4 stages; input in (ar,ai); result ends in (br,bi) original arrays.
__device__ __forceinline__ void fft1024_r4(
    float* ar, float* ai, float* br, float* bi,
    const float* twr, const float* twi, int t, int inv)
{
    int m = 1;
#pragma unroll
    for (int s = 0; s < 5; s++) {
        __syncthreads();
        fft_stage(ar, ai, br, bi, twr, twi, t, m, inv);
        float* tp;
        tp = ar; ar = br; br = tp;
        tp = ai; ai = bi; bi = tp;
        m <<= 2;
    }
    __syncthreads();
}

__device__ __forceinline__ void build_tw256(float* twr, float* twi, int t)
{
    float sn, cs;
    sincosf(-2.0f * (float)M_PI * (float)t * (1.0f / 1024.0f), &sn, &cs);
    twr[t] = cs; twi[t] = sn;
}

// ============================================================================
// bind + accumulate: Z = FFT(k + i*v); acc += Fk*Fv (Hermitian extraction)
// ============================================================================
__global__ void __launch_bounds__(256) bind_accum_kernel()
{
    __shared__ float twr[256], twi[256];
    __shared__ float reA[FBUF], imA[FBUF], reB[FBUF], imB[FBUF];

    const int t = threadIdx.x;
    const int c = blockIdx.x;
    const int b = blockIdx.y;
    build_tw256(twr, twi, t);

    float2 acc[4];
#pragma unroll
    for (int h = 0; h < 4; h++) acc[h] = make_float2(0.f, 0.f);

    const size_t base = ((size_t)b * SEQ + (size_t)c * CROWS) * DIM;
    for (int r = 0; r < CROWS; r++) {
        const float* kp = g_k + base + (size_t)r * DIM;
        const float* vp = g_v + base + (size_t)r * DIM;
#pragma unroll
        for (int h = 0; h < 4; h++) {
            const int i = t + (h << 8);
            reA[SK(i)] = kp[i];
            imA[SK(i)] = vp[i];
        }
        fft1024_r4(reA, imA, reB, imB, twr, twi, t, 0);   // Z in (reB,imB)
#pragma unroll
        for (int h = 0; h < 4; h++) {
            const int f  = t + (h << 8);
            const int fn = (1024 - f) & 1023;
            const float z1r = reB[SK(f)],  z1i = imB[SK(f)];
            const float z2r = reB[SK(fn)], z2i = imB[SK(fn)];
            const float Fkr = 0.5f * (z1r + z2r), Fki = 0.5f * (z1i - z2i);
            const float dx = z1r - z2r, dy = z1i + z2i;
            const float Fvr = 0.5f * dy, Fvi = -0.5f * dx;
            acc[h].x += fmaf(Fkr, Fvr, -Fki * Fvi);
            acc[h].y += fmaf(Fkr, Fvi,  Fki * Fvr);
        }
        __syncthreads();  // Z reads done before next iteration's FFT overwrites
    }

    float2* outp = g_part + ((size_t)b * NCH + c) * DIM;
#pragma unroll
    for (int h = 0; h < 4; h++) outp[t + (h << 8)] = acc[h];
}

__global__ void reduce_Fs_kernel()
{
    const int f = blockIdx.x * 256 + threadIdx.x;
    const int b = blockIdx.y;
    float2 s = make_float2(0.f, 0.f);
    const float2* p = g_part + (size_t)b * NCH * DIM + f;
    for (int c = 0; c < NCH; c++) {
        const float2 v = p[(size_t)c * DIM];
        s.x += v.x; s.y += v.y;
    }
    g_Fs[b * DIM + f] = s;
}

// ============================================================================
// output: Z = FFT(q + i*r); G = conj(Fq) - |Fr|^2; out = x + ifft(G*Fs).real
// ============================================================================
__global__ void __launch_bounds__(256) output_kernel(
    const float* __restrict__ x, float* __restrict__ out)
{
    __shared__ float twr[256], twi[256];
    __shared__ float reA[FBUF], imA[FBUF], reB[FBUF], imB[FBUF];

    const int t = threadIdx.x;
    const int row = blockIdx.x;
    const int b = row >> 12;
    build_tw256(twr, twi, t);

    const size_t base = (size_t)row * DIM;
    const float* qp = g_q + base;
    const float* rp = g_r + base;
#pragma unroll
    for (int h = 0; h < 4; h++) {
        const int i = t + (h << 8);
        reA[SK(i)] = qp[i];
        imA[SK(i)] = rp[i];
    }
    fft1024_r4(reA, imA, reB, imB, twr, twi, t, 0);   // Z in (reB,imB)

    const float2* Fsb = g_Fs + (size_t)b * DIM;
#pragma unroll
    for (int h = 0; h < 4; h++) {
        const int f  = t + (h << 8);
        const int fn = (1024 - f) & 1023;
        const float z1r = reB[SK(f)],  z1i = imB[SK(f)];
        const float z2r = reB[SK(fn)], z2i = imB[SK(fn)];
        const float Fqr = 0.5f * (z1r + z2r), Fqi = 0.5f * (z1i - z2i);
        const float dx = z1r - z2r, dy = z1i + z2i;
        const float Frr = 0.5f * dy, Fri = -0.5f * dx;
        const float mag2 = fmaf(Frr, Frr, Fri * Fri);
        const float Gr = Fqr - mag2, Gi = -Fqi;
        const float2 Fs = Fsb[f];
        // H = G * Fs -> write into A set (free)
        reA[SK(f)] = fmaf(Gr, Fs.x, -Gi * Fs.y);
        imA[SK(f)] = fmaf(Gr, Fs.y,  Gi * Fs.x);
    }
    // inverse FFT of H: first internal sync orders the H writes / Z reads
    fft1024_r4(reA, imA, reB, imB, twr, twi, t, 1);   // result in (reB,imB)

    const float* xp = x + base;
    float* op = out + base;
#pragma unroll
    for (int h = 0; h < 4; h++) {
        const int i = t + (h << 8);
        op[i] = xp[i] + reB[SK(i)] * (1.0f / 1024.0f);
    }
}

// ============================================================================
// Launch
// ============================================================================
extern "C" void kernel_launch(void* const* d_in, const int* in_sizes, int n_in,
                              void* d_out, int out_size)
{
    const float* x  = (const float*)d_in[0];
    const float* Wq = (const float*)d_in[1];
    const float* bq = (const float*)d_in[2];
    const float* Wk = (const float*)d_in[3];
    const float* bk = (const float*)d_in[4];
    const float* Wv = (const float*)d_in[5];
    const float* bv = (const float*)d_in[6];
    const float* Wr = (const float*)d_in[7];
    const float* br = (const float*)d_in[8];
    float* out = (float*)d_out;

    static bool attr_set = false;
    if (!attr_set) {
        cudaFuncSetAttribute(gemm_mma_kernel,
                             cudaFuncAttributeMaxDynamicSharedMemorySize, SMEM_DYN);
        attr_set = true;
    }

    convert_x_kernel<<<(MROWS * DIM) / 256, 256>>>(x);
    convert_w_kernel<<<dim3((DIM * DIM) / 256, 4), 256>>>(Wq, Wk, Wv, Wr);

    gemm_mma_kernel<<<dim3(DIM / BN, MROWS / BM, 4), 512, SMEM_DYN>>>(bq, bk, bv, br);

    bind_accum_kernel<<<dim3(NCH, BATCH), 256>>>();
    reduce_Fs_kernel<<<dim3(DIM / 256, BATCH), 256>>>();
    output_kernel<<<MROWS, 256>>>(x, out);
}

// round 6
// speedup vs baseline: 1.3647x; 1.3647x over previous
#include <cuda_runtime.h>
#include <cuda_fp16.h>
#include <math.h>
#include <stdint.h>

#define BATCH 4
#define SEQ   4096
#define DIM   1024
#define MROWS (BATCH*SEQ)       // 16384
#define KSTORE 2048             // A: [hi | lo] per row, fp16
#define NCH   256
#define CROWS (SEQ / NCH)       // 16

// ---- mma.sync GEMM tiling ----
#define BM 128
#define BN 256
#define KITERS 32               // 2048 effective K (2-term fp16 split)
#define STAGES 3
#define A_ST (BM * 128)         // 16384 B
#define B_ST (BN * 128)         // 32768 B
#define STAGE_B (A_ST + B_ST)   // 49152
#define SMEM_DYN (STAGES * STAGE_B)   // 147456

// -------- scratch (static device globals; no runtime allocation) -----------
__device__ __half g_xe[(size_t)MROWS * KSTORE];   // 64MB  [row][ah(1024)|al(1024)]
__device__ __half g_we[4][(size_t)DIM * DIM];     // 8MB   hi only
__device__ float  g_q[(size_t)MROWS * DIM];
__device__ float  g_k[(size_t)MROWS * DIM];
__device__ float  g_v[(size_t)MROWS * DIM];
__device__ float  g_r[(size_t)MROWS * DIM];
__device__ float2 g_part[BATCH * NCH * DIM];
__device__ float2 g_Fs[BATCH * DIM];

// ============================================================================
// helpers
// ============================================================================
__device__ __forceinline__ uint32_t smem_u32(const void* p) {
    uint32_t a;
    asm("{ .reg .u64 t; cvta.to.shared.u64 t, %1; cvt.u32.u64 %0, t; }" : "=r"(a) : "l"(p));
    return a;
}

__device__ __forceinline__ void cp16(uint32_t dst, const void* src) {
    asm volatile("cp.async.cg.shared.global [%0], [%1], 16;" :: "r"(dst), "l"(src) : "memory");
}
#define CP_COMMIT() asm volatile("cp.async.commit_group;" ::: "memory")
#define CP_WAIT1()  asm volatile("cp.async.wait_group 1;" ::: "memory")

__device__ __forceinline__ void ldmx4(uint32_t& r0, uint32_t& r1, uint32_t& r2, uint32_t& r3,
                                      uint32_t addr) {
    asm volatile("ldmatrix.sync.aligned.m8n8.x4.shared.b16 {%0,%1,%2,%3}, [%4];"
                 : "=r"(r0), "=r"(r1), "=r"(r2), "=r"(r3) : "r"(addr));
}

__device__ __forceinline__ void mma16816(float* c, uint32_t a0, uint32_t a1, uint32_t a2,
                                         uint32_t a3, uint32_t b0, uint32_t b1) {
    asm volatile(
        "mma.sync.aligned.m16n8k16.row.col.f32.f16.f16.f32 "
        "{%0,%1,%2,%3}, {%4,%5,%6,%7}, {%8,%9}, {%0,%1,%2,%3};"
        : "+f"(c[0]), "+f"(c[1]), "+f"(c[2]), "+f"(c[3])
        : "r"(a0), "r"(a1), "r"(a2), "r"(a3), "r"(b0), "r"(b1));
}

__device__ __forceinline__ float tanh_fast(float x) {
    float ax = fabsf(x);
    float e = __expf(-2.0f * ax);
    float t = __fdividef(1.0f - e, 1.0f + e);
    return copysignf(t, x);
}

// swizzled smem byte offset within a (rows x 128B) tile
__device__ __forceinline__ uint32_t swz(uint32_t row, uint32_t cg) {
    return row * 128u + ((cg ^ (row & 7u)) << 4);
}

// ============================================================================
// Conversion: x -> fp16 hi/lo halves ; W -> fp16 hi only
// ============================================================================
__global__ void __launch_bounds__(256) convert_x_kernel(const float* __restrict__ x)
{
    const size_t idx = (size_t)blockIdx.x * 256 + threadIdx.x;
    const size_t row = idx >> 10, d = idx & 1023;
    float v = x[idx];
    __half hi = __float2half(v);
    __half lo = __float2half(v - __half2float(hi));
    g_xe[row * KSTORE + d]        = hi;
    g_xe[row * KSTORE + 1024 + d] = lo;
}

__global__ void __launch_bounds__(256) convert_w_kernel(
    const float* __restrict__ Wq, const float* __restrict__ Wk,
    const float* __restrict__ Wv, const float* __restrict__ Wr)
{
    const int w = blockIdx.y;
    const float* W = (w == 0) ? Wq : (w == 1) ? Wk : (w == 2) ? Wv : Wr;
    const size_t idx = (size_t)blockIdx.x * 256 + threadIdx.x;
    g_we[w][idx] = __float2half(W[idx]);
}

// ============================================================================
// fp16 mma.sync GEMM, 2-term split: C = tanh(Ah@Bh^T + Al@Bh^T + bias)
// BM=128 x BN=256, 8 warps (warp 64x64). A chunks 0..31, B chunks kc&15.
// ============================================================================
__global__ void __launch_bounds__(256, 1) gemm_mma_kernel(
    const float* __restrict__ bq, const float* __restrict__ bk,
    const float* __restrict__ bv, const float* __restrict__ br)
{
    extern __shared__ char dsm[];
    const uint32_t smem = smem_u32(dsm);

    const int tid = threadIdx.x, wid = tid >> 5, lane = tid & 31;
    const int nb = blockIdx.x, mb = blockIdx.y, sel = blockIdx.z;
    const int wm = wid & 1, wn = wid >> 1;       // warp tile 64(m) x 64(n)
    const float* bias = (sel == 0) ? bq : (sel == 1) ? bk : (sel == 2) ? bv : br;
    float* C = (sel == 0) ? g_q : (sel == 1) ? g_k : (sel == 2) ? g_v : g_r;

    const char* a_base = (const char*)g_xe + (size_t)mb * BM * 4096;   // row stride 4096B
    const char* b_base = (const char*)g_we[sel] + (size_t)nb * BN * 2048; // row stride 2048B

    const uint32_t crow0 = (uint32_t)(tid >> 3);   // 0..31
    const uint32_t ccg = (uint32_t)(tid & 7);

    float acc[4][8][4];
#pragma unroll
    for (int i = 0; i < 4; i++)
#pragma unroll
        for (int j = 0; j < 8; j++)
#pragma unroll
            for (int q = 0; q < 4; q++) acc[i][j][q] = 0.f;

    auto issue = [&](int stage, int kc) {
        const int akc = kc;                 // 0..31 ([ah|al])
        const int bkc = kc & 15;            // B hi reused for both halves
        const uint32_t sA = smem + stage * STAGE_B;
        const uint32_t sB = sA + A_ST;
#pragma unroll
        for (int j = 0; j < 4; j++) {
            const uint32_t r = crow0 + 32u * j;
            cp16(sA + swz(r, ccg), a_base + (size_t)r * 4096 + akc * 128 + ccg * 16);
        }
#pragma unroll
        for (int j = 0; j < 8; j++) {
            const uint32_t r = crow0 + 32u * j;
            cp16(sB + swz(r, ccg), b_base + (size_t)r * 2048 + bkc * 128 + ccg * 16);
        }
    };

    issue(0, 0); CP_COMMIT();
    issue(1, 1); CP_COMMIT();

    const uint32_t a_row = (uint32_t)(wm * 64 + (lane & 15));
    const uint32_t a_kg  = (uint32_t)(lane >> 4);
    const uint32_t b_row = (uint32_t)(wn * 64 + (lane & 7) + ((lane >> 4) << 3));
    const uint32_t b_kg  = (uint32_t)((lane >> 3) & 1);

    for (int kc = 0; kc < KITERS; kc++) {
        const int s = kc % STAGES;
        CP_WAIT1();
        __syncthreads();
        const uint32_t sA = smem + s * STAGE_B;
        const uint32_t sB = sA + A_ST;
#pragma unroll
        for (int ks = 0; ks < 4; ks++) {
            uint32_t a[4][4];
#pragma unroll
            for (int mf = 0; mf < 4; mf++)
                ldmx4(a[mf][0], a[mf][1], a[mf][2], a[mf][3],
                      sA + swz(a_row + mf * 16, a_kg + ks * 2));
            uint32_t b[4][4];
#pragma unroll
            for (int nf2 = 0; nf2 < 4; nf2++)
                ldmx4(b[nf2][0], b[nf2][1], b[nf2][2], b[nf2][3],
                      sB + swz(b_row + nf2 * 16, b_kg + ks * 2));
#pragma unroll
            for (int mf = 0; mf < 4; mf++) {
#pragma unroll
                for (int nf2 = 0; nf2 < 4; nf2++) {
                    mma16816(acc[mf][nf2 * 2 + 0], a[mf][0], a[mf][1], a[mf][2], a[mf][3],
                             b[nf2][0], b[nf2][1]);
                    mma16816(acc[mf][nf2 * 2 + 1], a[mf][0], a[mf][1], a[mf][2], a[mf][3],
                             b[nf2][2], b[nf2][3]);
                }
            }
        }
        if (kc + 2 < KITERS) issue((kc + 2) % STAGES, kc + 2);
        CP_COMMIT();
    }

    // epilogue: bias + tanh + fp32 store
#pragma unroll
    for (int mf = 0; mf < 4; mf++) {
        const int r0 = mb * BM + wm * 64 + mf * 16 + (lane >> 2);
        const int r1 = r0 + 8;
#pragma unroll
        for (int nf = 0; nf < 8; nf++) {
            const int col = nb * BN + wn * 64 + nf * 8 + (lane & 3) * 2;
            const float2 b2 = *(const float2*)(bias + col);
            float2 o0, o1;
            o0.x = tanh_fast(acc[mf][nf][0] + b2.x);
            o0.y = tanh_fast(acc[mf][nf][1] + b2.y);
            o1.x = tanh_fast(acc[mf][nf][2] + b2.x);
            o1.y = tanh_fast(acc[mf][nf][3] + b2.y);
            *(float2*)(C + (size_t)r0 * DIM + col) = o0;
            *(float2*)(C + (size_t)r1 * DIM + col) = o1;
        }
    }
}

// ============================================================================
// Radix-4 Stockham FFT, N=1024, 256 threads, 5 stages (round-4 float2 version)
// ============================================================================
__device__ __forceinline__ float2 cmulf(float2 a, float2 b) {
    return make_float2(fmaf(a.x, b.x, -a.y * b.y), fmaf(a.x, b.y, a.y * b.x));
}
__device__ __forceinline__ float2 caddf(float2 a, float2 b) {
    return make_float2(a.x + b.x, a.y + b.y);
}
__device__ __forceinline__ float2 csubf(float2 a, float2 b) {
    return make_float2(a.x - b.x, a.y - b.y);
}

__device__ float2* fft1024_r4(float2* a, float2* b, const float2* tw, int t, int inv)
{
    int m = 1;
#pragma unroll
    for (int s = 0; s < 5; s++) {
        __syncthreads();
        const int k  = t & (m - 1);
        const int jm = t - k;
        const float2 x0 = a[t];
        const float2 x1 = a[t + 256];
        const float2 x2 = a[t + 512];
        const float2 x3 = a[t + 768];
        const float2 t0 = caddf(x0, x2);
        const float2 t1 = caddf(x1, x3);
        const float2 t2 = csubf(x0, x2);
        const float2 d  = csubf(x1, x3);
        const float2 t3 = inv ? make_float2(-d.y, d.x) : make_float2(d.y, -d.x);
        float2 w1 = tw[jm];
        if (inv) w1.y = -w1.y;
        const float2 w2 = cmulf(w1, w1);
        const float2 w3 = cmulf(w2, w1);
        const int o = 4 * jm + k;
        b[o]         = caddf(t0, t1);
        b[o + m]     = cmulf(w1, caddf(t2, t3));
        b[o + 2 * m] = cmulf(w2, csubf(t0, t1));
        b[o + 3 * m] = cmulf(w3, csubf(t2, t3));
        float2* tmp = a; a = b; b = tmp;
        m <<= 2;
    }
    __syncthreads();
    return a;
}

__device__ __forceinline__ void build_tw256(float2* tw, int t)
{
    float sn, cs;
    sincosf(-2.0f * (float)M_PI * (float)t * (1.0f / 1024.0f), &sn, &cs);
    tw[t] = make_float2(cs, sn);
}

// ============================================================================
// bind + accumulate: Z = FFT(k + i*v); acc += Fk*Fv (Hermitian extraction)
// ============================================================================
__global__ void __launch_bounds__(256) bind_accum_kernel()
{
    __shared__ float2 tw[256];
    __shared__ float2 bufA[1024];
    __shared__ float2 bufB[1024];

    const int t = threadIdx.x;
    const int c = blockIdx.x;
    const int b = blockIdx.y;
    build_tw256(tw, t);

    float2 acc[4];
#pragma unroll
    for (int h = 0; h < 4; h++) acc[h] = make_float2(0.f, 0.f);

    const size_t base = ((size_t)b * SEQ + (size_t)c * CROWS) * DIM;
    for (int r = 0; r < CROWS; r++) {
        const float* kp = g_k + base + (size_t)r * DIM;
        const float* vp = g_v + base + (size_t)r * DIM;
#pragma unroll
        for (int h = 0; h < 4; h++) {
            const int i = t + (h << 8);
            bufA[i] = make_float2(kp[i], vp[i]);
        }
        float2* Z = fft1024_r4(bufA, bufB, tw, t, 0);
#pragma unroll
        for (int h = 0; h < 4; h++) {
            const int f  = t + (h << 8);
            const int fn = (1024 - f) & 1023;
            const float2 z1 = Z[f];
            const float2 z2 = Z[fn];
            const float2 Fk = make_float2(0.5f * (z1.x + z2.x), 0.5f * (z1.y - z2.y));
            const float dx = z1.x - z2.x, dy = z1.y + z2.y;
            const float2 Fv = make_float2(0.5f * dy, -0.5f * dx);
            const float2 p = cmulf(Fk, Fv);
            acc[h].x += p.x; acc[h].y += p.y;
        }
        __syncthreads();
    }

    float2* outp = g_part + ((size_t)b * NCH + c) * DIM;
#pragma unroll
    for (int h = 0; h < 4; h++) outp[t + (h << 8)] = acc[h];
}

__global__ void reduce_Fs_kernel()
{
    const int f = blockIdx.x * 256 + threadIdx.x;
    const int b = blockIdx.y;
    float2 s = make_float2(0.f, 0.f);
    const float2* p = g_part + (size_t)b * NCH * DIM + f;
    for (int c = 0; c < NCH; c++) {
        const float2 v = p[(size_t)c * DIM];
        s.x += v.x; s.y += v.y;
    }
    g_Fs[b * DIM + f] = s;
}

// ============================================================================
// output: Z = FFT(q + i*r); G = conj(Fq) - |Fr|^2; out = x + ifft(G*Fs).real
// ============================================================================
__global__ void __launch_bounds__(256) output_kernel(
    const float* __restrict__ x, float* __restrict__ out)
{
    __shared__ float2 tw[256];
    __shared__ float2 bufA[1024];
    __shared__ float2 bufB[1024];

    const int t = threadIdx.x;
    const int row = blockIdx.x;
    const int b = row >> 12;
    build_tw256(tw, t);

    const size_t base = (size_t)row * DIM;
    const float* qp = g_q + base;
    const float* rp = g_r + base;
#pragma unroll
    for (int h = 0; h < 4; h++) {
        const int i = t + (h << 8);
        bufA[i] = make_float2(qp[i], rp[i]);
    }
    float2* Z = fft1024_r4(bufA, bufB, tw, t, 0);
    float2* other = (Z == bufA) ? bufB : bufA;

    const float2* Fsb = g_Fs + (size_t)b * DIM;
#pragma unroll
    for (int h = 0; h < 4; h++) {
        const int f  = t + (h << 8);
        const int fn = (1024 - f) & 1023;
        const float2 z1 = Z[f];
        const float2 z2 = Z[fn];
        const float2 Fq = make_float2(0.5f * (z1.x + z2.x), 0.5f * (z1.y - z2.y));
        const float dx = z1.x - z2.x, dy = z1.y + z2.y;
        const float2 Fr = make_float2(0.5f * dy, -0.5f * dx);
        const float mag2 = fmaf(Fr.x, Fr.x, Fr.y * Fr.y);
        const float2 G = make_float2(Fq.x - mag2, -Fq.y);
        other[f] = cmulf(G, Fsb[f]);
    }
    float2* res = fft1024_r4(other, Z, tw, t, 1);

    const float* xp = x + base;
    float* op = out + base;
#pragma unroll
    for (int h = 0; h < 4; h++) {
        const int i = t + (h << 8);
        op[i] = xp[i] + res[i].x * (1.0f / 1024.0f);
    }
}

// ============================================================================
// Launch
// ============================================================================
extern "C" void kernel_launch(void* const* d_in, const int* in_sizes, int n_in,
                              void* d_out, int out_size)
{
    const float* x  = (const float*)d_in[0];
    const float* Wq = (const float*)d_in[1];
    const float* bq = (const float*)d_in[2];
    const float* Wk = (const float*)d_in[3];
    const float* bk = (const float*)d_in[4];
    const float* Wv = (const float*)d_in[5];
    const float* bv = (const float*)d_in[6];
    const float* Wr = (const float*)d_in[7];
    const float* br = (const float*)d_in[8];
    float* out = (float*)d_out;

    static bool attr_set = false;
    if (!attr_set) {
        cudaFuncSetAttribute(gemm_mma_kernel,
                             cudaFuncAttributeMaxDynamicSharedMemorySize, SMEM_DYN);
        attr_set = true;
    }

    convert_x_kernel<<<(MROWS * DIM) / 256, 256>>>(x);
    convert_w_kernel<<<dim3((DIM * DIM) / 256, 4), 256>>>(Wq, Wk, Wv, Wr);

    gemm_mma_kernel<<<dim3(DIM / BN, MROWS / BM, 4), 256, SMEM_DYN>>>(bq, bk, bv, br);

    bind_accum_kernel<<<dim3(NCH, BATCH), 256>>>();
    reduce_Fs_kernel<<<dim3(DIM / 256, BATCH), 256>>>();
    output_kernel<<<MROWS, 256>>>(x, out);
}

// round 7
// speedup vs baseline: 1.4752x; 1.0810x over previous
#include <cuda_runtime.h>
#include <cuda_fp16.h>
#include <math.h>
#include <stdint.h>

#define BATCH 4
#define SEQ   4096
#define DIM   1024
#define MROWS (BATCH*SEQ)       // 16384
#define KSTORE 2048             // A: [hi | lo] per row, fp16
#define NCH   256
#define CROWS (SEQ / NCH)       // 16

// ---- mma.sync GEMM tiling ----
#define BM 128
#define BN 256
#define NB_CH 16                // B chunks (K=1024 / 64)
#define STAGES 3
#define A2_ST (2 * BM * 128)    // 32768 B (both A halves for this chunk)
#define B_ST (BN * 128)         // 32768 B
#define STAGE_B (A2_ST + B_ST)  // 65536
#define SMEM_DYN (STAGES * STAGE_B)   // 196608

// -------- scratch (static device globals; no runtime allocation) -----------
__device__ __half g_xe[(size_t)MROWS * KSTORE];   // 64MB  [row][ah(1024)|al(1024)]
__device__ __half g_we[4][(size_t)DIM * DIM];     // 8MB   hi only
__device__ float  g_q[(size_t)MROWS * DIM];
__device__ float  g_k[(size_t)MROWS * DIM];
__device__ float  g_v[(size_t)MROWS * DIM];
__device__ float  g_r[(size_t)MROWS * DIM];
__device__ float2 g_part[BATCH * NCH * DIM];
__device__ float2 g_Fs[BATCH * DIM];

// ============================================================================
// helpers
// ============================================================================
__device__ __forceinline__ uint32_t smem_u32(const void* p) {
    uint32_t a;
    asm("{ .reg .u64 t; cvta.to.shared.u64 t, %1; cvt.u32.u64 %0, t; }" : "=r"(a) : "l"(p));
    return a;
}

__device__ __forceinline__ void cp16(uint32_t dst, const void* src) {
    asm volatile("cp.async.cg.shared.global [%0], [%1], 16;" :: "r"(dst), "l"(src) : "memory");
}
#define CP_COMMIT() asm volatile("cp.async.commit_group;" ::: "memory")
#define CP_WAIT1()  asm volatile("cp.async.wait_group 1;" ::: "memory")

__device__ __forceinline__ void ldmx4(uint32_t& r0, uint32_t& r1, uint32_t& r2, uint32_t& r3,
                                      uint32_t addr) {
    asm volatile("ldmatrix.sync.aligned.m8n8.x4.shared.b16 {%0,%1,%2,%3}, [%4];"
                 : "=r"(r0), "=r"(r1), "=r"(r2), "=r"(r3) : "r"(addr));
}

__device__ __forceinline__ void mma16816(float* c, uint32_t a0, uint32_t a1, uint32_t a2,
                                         uint32_t a3, uint32_t b0, uint32_t b1) {
    asm volatile(
        "mma.sync.aligned.m16n8k16.row.col.f32.f16.f16.f32 "
        "{%0,%1,%2,%3}, {%4,%5,%6,%7}, {%8,%9}, {%0,%1,%2,%3};"
        : "+f"(c[0]), "+f"(c[1]), "+f"(c[2]), "+f"(c[3])
        : "r"(a0), "r"(a1), "r"(a2), "r"(a3), "r"(b0), "r"(b1));
}

__device__ __forceinline__ float tanh_fast(float x) {
    float ax = fabsf(x);
    float e = __expf(-2.0f * ax);
    float t = __fdividef(1.0f - e, 1.0f + e);
    return copysignf(t, x);
}

// swizzled smem byte offset within a (rows x 128B) tile
__device__ __forceinline__ uint32_t swz(uint32_t row, uint32_t cg) {
    return row * 128u + ((cg ^ (row & 7u)) << 4);
}

// ============================================================================
// Conversion: x -> fp16 hi/lo halves ; W -> fp16 hi only
// ============================================================================
__global__ void __launch_bounds__(256) convert_x_kernel(const float* __restrict__ x)
{
    const size_t idx = (size_t)blockIdx.x * 256 + threadIdx.x;
    const size_t row = idx >> 10, d = idx & 1023;
    float v = x[idx];
    __half hi = __float2half(v);
    __half lo = __float2half(v - __half2float(hi));
    g_xe[row * KSTORE + d]        = hi;
    g_xe[row * KSTORE + 1024 + d] = lo;
}

__global__ void __launch_bounds__(256) convert_w_kernel(
    const float* __restrict__ Wq, const float* __restrict__ Wk,
    const float* __restrict__ Wv, const float* __restrict__ Wr)
{
    const int w = blockIdx.y;
    const float* W = (w == 0) ? Wq : (w == 1) ? Wk : (w == 2) ? Wv : Wr;
    const size_t idx = (size_t)blockIdx.x * 256 + threadIdx.x;
    g_we[w][idx] = __float2half(W[idx]);
}

// ============================================================================
// fp16 mma.sync GEMM, 2-term split with B-chunk reuse:
//   per chunk bc: load B[bc] once + A_h[bc] + A_l[bc]; compute (ah+al)@b
// BM=128 x BN=256, 8 warps (warp 64x64), 16 iterations.
// ============================================================================
__global__ void __launch_bounds__(256, 1) gemm_mma_kernel(
    const float* __restrict__ bq, const float* __restrict__ bk,
    const float* __restrict__ bv, const float* __restrict__ br)
{
    extern __shared__ char dsm[];
    const uint32_t smem = smem_u32(dsm);

    const int tid = threadIdx.x, wid = tid >> 5, lane = tid & 31;
    const int nb = blockIdx.x, mb = blockIdx.y, sel = blockIdx.z;
    const int wm = wid & 1, wn = wid >> 1;       // warp tile 64(m) x 64(n)
    const float* bias = (sel == 0) ? bq : (sel == 1) ? bk : (sel == 2) ? bv : br;
    float* C = (sel == 0) ? g_q : (sel == 1) ? g_k : (sel == 2) ? g_v : g_r;

    const char* a_base = (const char*)g_xe + (size_t)mb * BM * 4096;      // 4096B/row
    const char* b_base = (const char*)g_we[sel] + (size_t)nb * BN * 2048; // 2048B/row

    const uint32_t crow0 = (uint32_t)(tid >> 3);   // 0..31
    const uint32_t ccg = (uint32_t)(tid & 7);

    float acc[4][8][4];
#pragma unroll
    for (int i = 0; i < 4; i++)
#pragma unroll
        for (int j = 0; j < 8; j++)
#pragma unroll
            for (int q = 0; q < 4; q++) acc[i][j][q] = 0.f;

    auto issue = [&](int stage, int bc) {
        const uint32_t sA = smem + stage * STAGE_B;
        const uint32_t sB = sA + A2_ST;
        // A: 256 logical rows (0-127 = ah chunk bc, 128-255 = al chunk bc)
#pragma unroll
        for (int j = 0; j < 8; j++) {
            const uint32_t r = crow0 + 32u * j;          // 0..255
            cp16(sA + swz(r, ccg),
                 a_base + (size_t)(r & 127u) * 4096 + bc * 128 + (r >> 7) * 2048 + ccg * 16);
        }
        // B: 256 rows
#pragma unroll
        for (int j = 0; j < 8; j++) {
            const uint32_t r = crow0 + 32u * j;
            cp16(sB + swz(r, ccg), b_base + (size_t)r * 2048 + bc * 128 + ccg * 16);
        }
    };

    issue(0, 0); CP_COMMIT();
    issue(1, 1); CP_COMMIT();

    const uint32_t a_row = (uint32_t)(wm * 64 + (lane & 15));
    const uint32_t a_kg  = (uint32_t)(lane >> 4);
    const uint32_t b_row = (uint32_t)(wn * 64 + (lane & 7) + ((lane >> 4) << 3));
    const uint32_t b_kg  = (uint32_t)((lane >> 3) & 1);

    for (int bc = 0; bc < NB_CH; bc++) {
        const int s = bc % STAGES;
        CP_WAIT1();
        __syncthreads();
        const uint32_t sA = smem + s * STAGE_B;
        const uint32_t sB = sA + A2_ST;
#pragma unroll
        for (int ks = 0; ks < 4; ks++) {
            uint32_t b[4][4];
#pragma unroll
            for (int nf2 = 0; nf2 < 4; nf2++)
                ldmx4(b[nf2][0], b[nf2][1], b[nf2][2], b[nf2][3],
                      sB + swz(b_row + nf2 * 16, b_kg + ks * 2));
#pragma unroll
            for (int half = 0; half < 2; half++) {
                uint32_t a[4][4];
#pragma unroll
                for (int mf = 0; mf < 4; mf++)
                    ldmx4(a[mf][0], a[mf][1], a[mf][2], a[mf][3],
                          sA + half * (BM * 128) + swz(a_row + mf * 16, a_kg + ks * 2));
#pragma unroll
                for (int mf = 0; mf < 4; mf++) {
#pragma unroll
                    for (int nf2 = 0; nf2 < 4; nf2++) {
                        mma16816(acc[mf][nf2 * 2 + 0], a[mf][0], a[mf][1], a[mf][2], a[mf][3],
                                 b[nf2][0], b[nf2][1]);
                        mma16816(acc[mf][nf2 * 2 + 1], a[mf][0], a[mf][1], a[mf][2], a[mf][3],
                                 b[nf2][2], b[nf2][3]);
                    }
                }
            }
        }
        if (bc + 2 < NB_CH) issue((bc + 2) % STAGES, bc + 2);
        CP_COMMIT();
    }

    // epilogue: bias + tanh + fp32 store
#pragma unroll
    for (int mf = 0; mf < 4; mf++) {
        const int r0 = mb * BM + wm * 64 + mf * 16 + (lane >> 2);
        const int r1 = r0 + 8;
#pragma unroll
        for (int nf = 0; nf < 8; nf++) {
            const int col = nb * BN + wn * 64 + nf * 8 + (lane & 3) * 2;
            const float2 b2 = *(const float2*)(bias + col);
            float2 o0, o1;
            o0.x = tanh_fast(acc[mf][nf][0] + b2.x);
            o0.y = tanh_fast(acc[mf][nf][1] + b2.y);
            o1.x = tanh_fast(acc[mf][nf][2] + b2.x);
            o1.y = tanh_fast(acc[mf][nf][3] + b2.y);
            *(float2*)(C + (size_t)r0 * DIM + col) = o0;
            *(float2*)(C + (size_t)r1 * DIM + col) = o1;
        }
    }
}

// ============================================================================
// Radix-4 Stockham FFT, N=1024, 256 threads.
// Stage 1 (m=1) fused with data load; remaining 4 stages via fft_tail<4>.
// tw[e] = exp(-2*pi*i*e/1024), e in [0,256).
// ============================================================================
__device__ __forceinline__ float2 cmulf(float2 a, float2 b) {
    return make_float2(fmaf(a.x, b.x, -a.y * b.y), fmaf(a.x, b.y, a.y * b.x));
}
__device__ __forceinline__ float2 caddf(float2 a, float2 b) {
    return make_float2(a.x + b.x, a.y + b.y);
}
__device__ __forceinline__ float2 csubf(float2 a, float2 b) {
    return make_float2(a.x - b.x, a.y - b.y);
}

// first radix-4 stage (m=1) on 4 register inputs, writes dst[4t..4t+3]
__device__ __forceinline__ void fft_stage1_store(
    float2 x0, float2 x1, float2 x2, float2 x3,
    float2* dst, const float2* tw, int t, int inv)
{
    const float2 t0 = caddf(x0, x2);
    const float2 t1 = caddf(x1, x3);
    const float2 t2 = csubf(x0, x2);
    const float2 d  = csubf(x1, x3);
    const float2 t3 = inv ? make_float2(-d.y, d.x) : make_float2(d.y, -d.x);
    float2 w1 = tw[t];                  // own thread's entry (no sync needed)
    if (inv) w1.y = -w1.y;
    const float2 w2 = cmulf(w1, w1);
    const float2 w3 = cmulf(w2, w1);
    const int o = 4 * t;
    dst[o]     = caddf(t0, t1);
    dst[o + 1] = cmulf(w1, caddf(t2, t3));
    dst[o + 2] = cmulf(w2, csubf(t0, t1));
    dst[o + 3] = cmulf(w3, csubf(t2, t3));
}

// NS radix-4 stages starting at m = m0; returns buffer holding the result.
template <int NS>
__device__ float2* fft_tail(float2* a, float2* b, const float2* tw, int t, int inv, int m0)
{
    int m = m0;
#pragma unroll
    for (int s = 0; s < NS; s++) {
        __syncthreads();
        const int k  = t & (m - 1);
        const int jm = t - k;
        const float2 x0 = a[t];
        const float2 x1 = a[t + 256];
        const float2 x2 = a[t + 512];
        const float2 x3 = a[t + 768];
        const float2 t0 = caddf(x0, x2);
        const float2 t1 = caddf(x1, x3);
        const float2 t2 = csubf(x0, x2);
        const float2 d  = csubf(x1, x3);
        const float2 t3 = inv ? make_float2(-d.y, d.x) : make_float2(d.y, -d.x);
        float2 w1 = tw[jm];
        if (inv) w1.y = -w1.y;
        const float2 w2 = cmulf(w1, w1);
        const float2 w3 = cmulf(w2, w1);
        const int o = 4 * jm + k;
        b[o]         = caddf(t0, t1);
        b[o + m]     = cmulf(w1, caddf(t2, t3));
        b[o + 2 * m] = cmulf(w2, csubf(t0, t1));
        b[o + 3 * m] = cmulf(w3, csubf(t2, t3));
        float2* tmp = a; a = b; b = tmp;
        m <<= 2;
    }
    __syncthreads();
    return a;
}

__device__ __forceinline__ void build_tw256(float2* tw, int t)
{
    float sn, cs;
    sincosf(-2.0f * (float)M_PI * (float)t * (1.0f / 1024.0f), &sn, &cs);
    tw[t] = make_float2(cs, sn);
}

// ============================================================================
// bind + accumulate: Z = FFT(k + i*v); acc += Fk*Fv (Hermitian extraction)
// ============================================================================
__global__ void __launch_bounds__(256) bind_accum_kernel()
{
    __shared__ float2 tw[256];
    __shared__ float2 bufA[1024];
    __shared__ float2 bufB[1024];

    const int t = threadIdx.x;
    const int c = blockIdx.x;
    const int b = blockIdx.y;
    build_tw256(tw, t);

    float2 acc[4];
#pragma unroll
    for (int h = 0; h < 4; h++) acc[h] = make_float2(0.f, 0.f);

    const size_t base = ((size_t)b * SEQ + (size_t)c * CROWS) * DIM;
    for (int r = 0; r < CROWS; r++) {
        const float* kp = g_k + base + (size_t)r * DIM;
        const float* vp = g_v + base + (size_t)r * DIM;
        // fused stage 1: load 4 points from global, butterfly, write bufA
        fft_stage1_store(
            make_float2(kp[t],       vp[t]),
            make_float2(kp[t + 256], vp[t + 256]),
            make_float2(kp[t + 512], vp[t + 512]),
            make_float2(kp[t + 768], vp[t + 768]),
            bufA, tw, t, 0);
        float2* Z = fft_tail<4>(bufA, bufB, tw, t, 0, 4);   // Z = bufA
#pragma unroll
        for (int h = 0; h < 4; h++) {
            const int f  = t + (h << 8);
            const int fn = (1024 - f) & 1023;
            const float2 z1 = Z[f];
            const float2 z2 = Z[fn];
            const float2 Fk = make_float2(0.5f * (z1.x + z2.x), 0.5f * (z1.y - z2.y));
            const float dx = z1.x - z2.x, dy = z1.y + z2.y;
            const float2 Fv = make_float2(0.5f * dy, -0.5f * dx);
            const float2 p = cmulf(Fk, Fv);
            acc[h].x += p.x; acc[h].y += p.y;
        }
        __syncthreads();   // Z reads done before next row's stage1 overwrites
    }

    float2* outp = g_part + ((size_t)b * NCH + c) * DIM;
#pragma unroll
    for (int h = 0; h < 4; h++) outp[t + (h << 8)] = acc[h];
}

__global__ void reduce_Fs_kernel()
{
    const int f = blockIdx.x * 256 + threadIdx.x;
    const int b = blockIdx.y;
    float2 s = make_float2(0.f, 0.f);
    const float2* p = g_part + (size_t)b * NCH * DIM + f;
    for (int c = 0; c < NCH; c++) {
        const float2 v = p[(size_t)c * DIM];
        s.x += v.x; s.y += v.y;
    }
    g_Fs[b * DIM + f] = s;
}

// ============================================================================
// output: Z = FFT(q + i*r); G = conj(Fq) - |Fr|^2; out = x + ifft(G*Fs).real
// Inverse FFT stage 1 fused with the pointwise H = G*Fs computation.
// ============================================================================
__global__ void __launch_bounds__(256) output_kernel(
    const float* __restrict__ x, float* __restrict__ out)
{
    __shared__ float2 tw[256];
    __shared__ float2 bufA[1024];
    __shared__ float2 bufB[1024];

    const int t = threadIdx.x;
    const int row = blockIdx.x;
    const int b = row >> 12;
    build_tw256(tw, t);

    const size_t base = (size_t)row * DIM;
    const float* qp = g_q + base;
    const float* rp = g_r + base;
    // fused forward stage 1
    fft_stage1_store(
        make_float2(qp[t],       rp[t]),
        make_float2(qp[t + 256], rp[t + 256]),
        make_float2(qp[t + 512], rp[t + 512]),
        make_float2(qp[t + 768], rp[t + 768]),
        bufA, tw, t, 0);
    float2* Z = fft_tail<4>(bufA, bufB, tw, t, 0, 4);     // Z = bufA

    const float2* Fsb = g_Fs + (size_t)b * DIM;
    // compute H[t + h*256] in registers (exactly the inverse stage-1 inputs)
    float2 Hreg[4];
#pragma unroll
    for (int h = 0; h < 4; h++) {
        const int f  = t + (h << 8);
        const int fn = (1024 - f) & 1023;
        const float2 z1 = Z[f];
        const float2 z2 = Z[fn];
        const float2 Fq = make_float2(0.5f * (z1.x + z2.x), 0.5f * (z1.y - z2.y));
        const float dx = z1.x - z2.x, dy = z1.y + z2.y;
        const float2 Fr = make_float2(0.5f * dy, -0.5f * dx);
        const float mag2 = fmaf(Fr.x, Fr.x, Fr.y * Fr.y);
        const float2 G = make_float2(Fq.x - mag2, -Fq.y);
        Hreg[h] = cmulf(G, Fsb[f]);
    }
    // fused inverse stage 1 -> bufB (free: last reads of bufB finished in tail)
    fft_stage1_store(Hreg[0], Hreg[1], Hreg[2], Hreg[3], bufB, tw, t, 1);
    float2* res = fft_tail<4>(bufB, bufA, tw, t, 1, 4);   // res = bufB

    const float* xp = x + base;
    float* op = out + base;
#pragma unroll
    for (int h = 0; h < 4; h++) {
        const int i = t + (h << 8);
        op[i] = xp[i] + res[i].x * (1.0f / 1024.0f);
    }
}

// ============================================================================
// Launch
// ============================================================================
extern "C" void kernel_launch(void* const* d_in, const int* in_sizes, int n_in,
                              void* d_out, int out_size)
{
    const float* x  = (const float*)d_in[0];
    const float* Wq = (const float*)d_in[1];
    const float* bq = (const float*)d_in[2];
    const float* Wk = (const float*)d_in[3];
    const float* bk = (const float*)d_in[4];
    const float* Wv = (const float*)d_in[5];
    const float* bv = (const float*)d_in[6];
    const float* Wr = (const float*)d_in[7];
    const float* br = (const float*)d_in[8];
    float* out = (float*)d_out;

    static bool attr_set = false;
    if (!attr_set) {
        cudaFuncSetAttribute(gemm_mma_kernel,
                             cudaFuncAttributeMaxDynamicSharedMemorySize, SMEM_DYN);
        attr_set = true;
    }

    convert_x_kernel<<<(MROWS * DIM) / 256, 256>>>(x);
    convert_w_kernel<<<dim3((DIM * DIM) / 256, 4), 256>>>(Wq, Wk, Wv, Wr);

    gemm_mma_kernel<<<dim3(DIM / BN, MROWS / BM, 4), 256, SMEM_DYN>>>(bq, bk, bv, br);

    bind_accum_kernel<<<dim3(NCH, BATCH), 256>>>();
    reduce_Fs_kernel<<<dim3(DIM / 256, BATCH), 256>>>();
    output_kernel<<<MROWS, 256>>>(x, out);
}

// round 8
// speedup vs baseline: 1.5283x; 1.0360x over previous
#include <cuda_runtime.h>
#include <cuda_fp16.h>
#include <math.h>
#include <stdint.h>

#define BATCH 4
#define SEQ   4096
#define DIM   1024
#define MROWS (BATCH*SEQ)       // 16384
#define KSTORE 2048             // A: [hi | lo] per row, fp16
#define NCH   256
#define CROWS (SEQ / NCH)       // 16

// ---- mma.sync GEMM tiling ----
#define BM 128
#define BN 256
#define NB_CH 16                // B chunks (K=1024 / 64)
#define STAGES 3
#define A2_ST (2 * BM * 128)    // 32768 B (both A halves for this chunk)
#define B_ST (BN * 128)         // 32768 B
#define STAGE_B (A2_ST + B_ST)  // 65536
#define SMEM_DYN (STAGES * STAGE_B)   // 196608

// -------- scratch (static device globals; no runtime allocation) -----------
__device__ __half g_xe[(size_t)MROWS * KSTORE];   // 64MB  [row][ah(1024)|al(1024)]
__device__ __half g_we[4][(size_t)DIM * DIM];     // 8MB   hi only
__device__ float  g_q[(size_t)MROWS * DIM];
__device__ float  g_k[(size_t)MROWS * DIM];
__device__ float  g_v[(size_t)MROWS * DIM];
__device__ float  g_r[(size_t)MROWS * DIM];
__device__ float2 g_part[BATCH * NCH * DIM];
__device__ float2 g_Fs[BATCH * DIM];

// ============================================================================
// helpers
// ============================================================================
__device__ __forceinline__ uint32_t smem_u32(const void* p) {
    uint32_t a;
    asm("{ .reg .u64 t; cvta.to.shared.u64 t, %1; cvt.u32.u64 %0, t; }" : "=r"(a) : "l"(p));
    return a;
}

__device__ __forceinline__ void cp16(uint32_t dst, const void* src) {
    asm volatile("cp.async.cg.shared.global [%0], [%1], 16;" :: "r"(dst), "l"(src) : "memory");
}
#define CP_COMMIT() asm volatile("cp.async.commit_group;" ::: "memory")
#define CP_WAIT1()  asm volatile("cp.async.wait_group 1;" ::: "memory")

__device__ __forceinline__ void ldmx4(uint32_t& r0, uint32_t& r1, uint32_t& r2, uint32_t& r3,
                                      uint32_t addr) {
    asm volatile("ldmatrix.sync.aligned.m8n8.x4.shared.b16 {%0,%1,%2,%3}, [%4];"
                 : "=r"(r0), "=r"(r1), "=r"(r2), "=r"(r3) : "r"(addr));
}

__device__ __forceinline__ void mma16816(float* c, uint32_t a0, uint32_t a1, uint32_t a2,
                                         uint32_t a3, uint32_t b0, uint32_t b1) {
    asm volatile(
        "mma.sync.aligned.m16n8k16.row.col.f32.f16.f16.f32 "
        "{%0,%1,%2,%3}, {%4,%5,%6,%7}, {%8,%9}, {%0,%1,%2,%3};"
        : "+f"(c[0]), "+f"(c[1]), "+f"(c[2]), "+f"(c[3])
        : "r"(a0), "r"(a1), "r"(a2), "r"(a3), "r"(b0), "r"(b1));
}

__device__ __forceinline__ float tanh_fast(float x) {
    float ax = fabsf(x);
    float e = __expf(-2.0f * ax);
    float t = __fdividef(1.0f - e, 1.0f + e);
    return copysignf(t, x);
}

// swizzled smem byte offset within a (rows x 128B) tile
__device__ __forceinline__ uint32_t swz(uint32_t row, uint32_t cg) {
    return row * 128u + ((cg ^ (row & 7u)) << 4);
}

// ============================================================================
// Conversion: x -> fp16 hi/lo halves ; W -> fp16 hi only  (x4 vectorized)
// ============================================================================
__global__ void __launch_bounds__(256) convert_x_kernel(const float* __restrict__ x)
{
    const size_t base = ((size_t)blockIdx.x * 256 + threadIdx.x) * 4;
    const size_t row = base >> 10, d = base & 1023;
    const float4 v = *(const float4*)(x + base);
    __half2 hi0 = make_half2(__float2half(v.x), __float2half(v.y));
    __half2 hi1 = make_half2(__float2half(v.z), __float2half(v.w));
    __half2 lo0 = make_half2(__float2half(v.x - __half2float(hi0.x)),
                             __float2half(v.y - __half2float(hi0.y)));
    __half2 lo1 = make_half2(__float2half(v.z - __half2float(hi1.x)),
                             __float2half(v.w - __half2float(hi1.y)));
    __half2* ph = (__half2*)(g_xe + row * KSTORE + d);
    __half2* pl = (__half2*)(g_xe + row * KSTORE + 1024 + d);
    ph[0] = hi0; ph[1] = hi1;
    pl[0] = lo0; pl[1] = lo1;
}

__global__ void __launch_bounds__(256) convert_w_kernel(
    const float* __restrict__ Wq, const float* __restrict__ Wk,
    const float* __restrict__ Wv, const float* __restrict__ Wr)
{
    const int w = blockIdx.y;
    const float* W = (w == 0) ? Wq : (w == 1) ? Wk : (w == 2) ? Wv : Wr;
    const size_t base = ((size_t)blockIdx.x * 256 + threadIdx.x) * 4;
    const float4 v = *(const float4*)(W + base);
    __half2 h0 = make_half2(__float2half(v.x), __float2half(v.y));
    __half2 h1 = make_half2(__float2half(v.z), __float2half(v.w));
    __half2* p = (__half2*)(g_we[w] + base);
    p[0] = h0; p[1] = h1;
}

// ============================================================================
// fp16 mma.sync GEMM, 2-term split with B-chunk reuse + early prefetch +
// B-fragment double buffering. BM=128 x BN=256, 8 warps (warp 64x64).
// ============================================================================
__global__ void __launch_bounds__(256, 1) gemm_mma_kernel(
    const float* __restrict__ bq, const float* __restrict__ bk,
    const float* __restrict__ bv, const float* __restrict__ br)
{
    extern __shared__ char dsm[];
    const uint32_t smem = smem_u32(dsm);

    const int tid = threadIdx.x, wid = tid >> 5, lane = tid & 31;
    const int nb = blockIdx.x, mb = blockIdx.y, sel = blockIdx.z;
    const int wm = wid & 1, wn = wid >> 1;       // warp tile 64(m) x 64(n)
    const float* bias = (sel == 0) ? bq : (sel == 1) ? bk : (sel == 2) ? bv : br;
    float* C = (sel == 0) ? g_q : (sel == 1) ? g_k : (sel == 2) ? g_v : g_r;

    const char* a_base = (const char*)g_xe + (size_t)mb * BM * 4096;      // 4096B/row
    const char* b_base = (const char*)g_we[sel] + (size_t)nb * BN * 2048; // 2048B/row

    const uint32_t crow0 = (uint32_t)(tid >> 3);   // 0..31
    const uint32_t ccg = (uint32_t)(tid & 7);

    float acc[4][8][4];
#pragma unroll
    for (int i = 0; i < 4; i++)
#pragma unroll
        for (int j = 0; j < 8; j++)
#pragma unroll
            for (int q = 0; q < 4; q++) acc[i][j][q] = 0.f;

    auto issue = [&](int stage, int bc) {
        const uint32_t sA = smem + stage * STAGE_B;
        const uint32_t sB = sA + A2_ST;
#pragma unroll
        for (int j = 0; j < 8; j++) {
            const uint32_t r = crow0 + 32u * j;          // 0..255
            cp16(sA + swz(r, ccg),
                 a_base + (size_t)(r & 127u) * 4096 + bc * 128 + (r >> 7) * 2048 + ccg * 16);
        }
#pragma unroll
        for (int j = 0; j < 8; j++) {
            const uint32_t r = crow0 + 32u * j;
            cp16(sB + swz(r, ccg), b_base + (size_t)r * 2048 + bc * 128 + ccg * 16);
        }
    };

    issue(0, 0); CP_COMMIT();
    issue(1, 1); CP_COMMIT();

    const uint32_t a_row = (uint32_t)(wm * 64 + (lane & 15));
    const uint32_t a_kg  = (uint32_t)(lane >> 4);
    const uint32_t b_row = (uint32_t)(wn * 64 + (lane & 7) + ((lane >> 4) << 3));
    const uint32_t b_kg  = (uint32_t)((lane >> 3) & 1);

    for (int bc = 0; bc < NB_CH; bc++) {
        const int s = bc % STAGES;
        CP_WAIT1();
        __syncthreads();
        // early prefetch: the target stage was consumed last iteration
        if (bc + 2 < NB_CH) issue((bc + 2) % STAGES, bc + 2);
        CP_COMMIT();                     // always commit (possibly empty group)

        const uint32_t sA = smem + s * STAGE_B;
        const uint32_t sB = sA + A2_ST;

        uint32_t bfr[2][4][4];           // double-buffered B fragments
#pragma unroll
        for (int nf2 = 0; nf2 < 4; nf2++)
            ldmx4(bfr[0][nf2][0], bfr[0][nf2][1], bfr[0][nf2][2], bfr[0][nf2][3],
                  sB + swz(b_row + nf2 * 16, b_kg));

#pragma unroll
        for (int ks = 0; ks < 4; ks++) {
            const int cur = ks & 1, nxt = cur ^ 1;
            uint32_t a0[4][4], a1[4][4];
#pragma unroll
            for (int mf = 0; mf < 4; mf++)
                ldmx4(a0[mf][0], a0[mf][1], a0[mf][2], a0[mf][3],
                      sA + swz(a_row + mf * 16, a_kg + ks * 2));
#pragma unroll
            for (int mf = 0; mf < 4; mf++)
                ldmx4(a1[mf][0], a1[mf][1], a1[mf][2], a1[mf][3],
                      sA + (BM * 128) + swz(a_row + mf * 16, a_kg + ks * 2));
            // MMA half0 (hi)
#pragma unroll
            for (int mf = 0; mf < 4; mf++) {
#pragma unroll
                for (int nf2 = 0; nf2 < 4; nf2++) {
                    mma16816(acc[mf][nf2 * 2 + 0], a0[mf][0], a0[mf][1], a0[mf][2], a0[mf][3],
                             bfr[cur][nf2][0], bfr[cur][nf2][1]);
                    mma16816(acc[mf][nf2 * 2 + 1], a0[mf][0], a0[mf][1], a0[mf][2], a0[mf][3],
                             bfr[cur][nf2][2], bfr[cur][nf2][3]);
                }
            }
            // prefetch next ks B fragments under the half1 MMAs
            if (ks < 3) {
#pragma unroll
                for (int nf2 = 0; nf2 < 4; nf2++)
                    ldmx4(bfr[nxt][nf2][0], bfr[nxt][nf2][1], bfr[nxt][nf2][2], bfr[nxt][nf2][3],
                          sB + swz(b_row + nf2 * 16, b_kg + (ks + 1) * 2));
            }
            // MMA half1 (lo)
#pragma unroll
            for (int mf = 0; mf < 4; mf++) {
#pragma unroll
                for (int nf2 = 0; nf2 < 4; nf2++) {
                    mma16816(acc[mf][nf2 * 2 + 0], a1[mf][0], a1[mf][1], a1[mf][2], a1[mf][3],
                             bfr[cur][nf2][0], bfr[cur][nf2][1]);
                    mma16816(acc[mf][nf2 * 2 + 1], a1[mf][0], a1[mf][1], a1[mf][2], a1[mf][3],
                             bfr[cur][nf2][2], bfr[cur][nf2][3]);
                }
            }
        }
    }

    // epilogue: bias + tanh + fp32 store
#pragma unroll
    for (int mf = 0; mf < 4; mf++) {
        const int r0 = mb * BM + wm * 64 + mf * 16 + (lane >> 2);
        const int r1 = r0 + 8;
#pragma unroll
        for (int nf = 0; nf < 8; nf++) {
            const int col = nb * BN + wn * 64 + nf * 8 + (lane & 3) * 2;
            const float2 b2 = *(const float2*)(bias + col);
            float2 o0, o1;
            o0.x = tanh_fast(acc[mf][nf][0] + b2.x);
            o0.y = tanh_fast(acc[mf][nf][1] + b2.y);
            o1.x = tanh_fast(acc[mf][nf][2] + b2.x);
            o1.y = tanh_fast(acc[mf][nf][3] + b2.y);
            *(float2*)(C + (size_t)r0 * DIM + col) = o0;
            *(float2*)(C + (size_t)r1 * DIM + col) = o1;
        }
    }
}

// ============================================================================
// Radix-4 Stockham FFT, N=1024, 256 threads.
// Stage 1 (m=1) fused with data source; remaining 4 stages via fft_tail<4>.
// tw[e] = exp(-2*pi*i*e/1024), e in [0,256).
// ============================================================================
__device__ __forceinline__ float2 cmulf(float2 a, float2 b) {
    return make_float2(fmaf(a.x, b.x, -a.y * b.y), fmaf(a.x, b.y, a.y * b.x));
}
__device__ __forceinline__ float2 caddf(float2 a, float2 b) {
    return make_float2(a.x + b.x, a.y + b.y);
}
__device__ __forceinline__ float2 csubf(float2 a, float2 b) {
    return make_float2(a.x - b.x, a.y - b.y);
}

// first radix-4 stage (m=1) on 4 register inputs; float4 stores
__device__ __forceinline__ void fft_stage1_store(
    float2 x0, float2 x1, float2 x2, float2 x3,
    float2* dst, const float2* tw, int t, int inv)
{
    const float2 t0 = caddf(x0, x2);
    const float2 t1 = caddf(x1, x3);
    const float2 t2 = csubf(x0, x2);
    const float2 d  = csubf(x1, x3);
    const float2 t3 = inv ? make_float2(-d.y, d.x) : make_float2(d.y, -d.x);
    float2 w1 = tw[t];
    if (inv) w1.y = -w1.y;
    const float2 w2 = cmulf(w1, w1);
    const float2 w3 = cmulf(w2, w1);
    const float2 y0 = caddf(t0, t1);
    const float2 y1 = cmulf(w1, caddf(t2, t3));
    const float2 y2 = cmulf(w2, csubf(t0, t1));
    const float2 y3 = cmulf(w3, csubf(t2, t3));
    float4* d4 = (float4*)(dst + 4 * t);
    d4[0] = make_float4(y0.x, y0.y, y1.x, y1.y);
    d4[1] = make_float4(y2.x, y2.y, y3.x, y3.y);
}

// NS radix-4 stages starting at m = m0; returns buffer holding the result.
template <int NS>
__device__ float2* fft_tail(float2* a, float2* b, const float2* tw, int t, int inv, int m0)
{
    int m = m0;
#pragma unroll
    for (int s = 0; s < NS; s++) {
        __syncthreads();
        const int k  = t & (m - 1);
        const int jm = t - k;
        const float2 x0 = a[t];
        const float2 x1 = a[t + 256];
        const float2 x2 = a[t + 512];
        const float2 x3 = a[t + 768];
        const float2 t0 = caddf(x0, x2);
        const float2 t1 = caddf(x1, x3);
        const float2 t2 = csubf(x0, x2);
        const float2 d  = csubf(x1, x3);
        const float2 t3 = inv ? make_float2(-d.y, d.x) : make_float2(d.y, -d.x);
        float2 w1 = tw[jm];
        if (inv) w1.y = -w1.y;
        const float2 w2 = cmulf(w1, w1);
        const float2 w3 = cmulf(w2, w1);
        const int o = 4 * jm + k;
        b[o]         = caddf(t0, t1);
        b[o + m]     = cmulf(w1, caddf(t2, t3));
        b[o + 2 * m] = cmulf(w2, csubf(t0, t1));
        b[o + 3 * m] = cmulf(w3, csubf(t2, t3));
        float2* tmp = a; a = b; b = tmp;
        m <<= 2;
    }
    __syncthreads();
    return a;
}

__device__ __forceinline__ void build_tw256(float2* tw, int t)
{
    float sn, cs;
    sincosf(-2.0f * (float)M_PI * (float)t * (1.0f / 1024.0f), &sn, &cs);
    tw[t] = make_float2(cs, sn);
}

// ============================================================================
// bind + accumulate: Z = FFT(k + i*v); acc += Fk*Fv (Hermitian extraction)
// ============================================================================
__global__ void __launch_bounds__(256) bind_accum_kernel()
{
    __shared__ float2 tw[256];
    __shared__ float2 bufA[1024];
    __shared__ float2 bufB[1024];

    const int t = threadIdx.x;
    const int c = blockIdx.x;
    const int b = blockIdx.y;
    build_tw256(tw, t);

    float2 acc[4];
#pragma unroll
    for (int h = 0; h < 4; h++) acc[h] = make_float2(0.f, 0.f);

    const size_t base = ((size_t)b * SEQ + (size_t)c * CROWS) * DIM;
    for (int r = 0; r < CROWS; r++) {
        const float* kp = g_k + base + (size_t)r * DIM;
        const float* vp = g_v + base + (size_t)r * DIM;
        fft_stage1_store(
            make_float2(kp[t],       vp[t]),
            make_float2(kp[t + 256], vp[t + 256]),
            make_float2(kp[t + 512], vp[t + 512]),
            make_float2(kp[t + 768], vp[t + 768]),
            bufA, tw, t, 0);
        float2* Z = fft_tail<4>(bufA, bufB, tw, t, 0, 4);   // Z = bufA
#pragma unroll
        for (int h = 0; h < 4; h++) {
            const int f  = t + (h << 8);
            const int fn = (1024 - f) & 1023;
            const float2 z1 = Z[f];
            const float2 z2 = Z[fn];
            const float2 Fk = make_float2(0.5f * (z1.x + z2.x), 0.5f * (z1.y - z2.y));
            const float dx = z1.x - z2.x, dy = z1.y + z2.y;
            const float2 Fv = make_float2(0.5f * dy, -0.5f * dx);
            const float2 p = cmulf(Fk, Fv);
            acc[h].x += p.x; acc[h].y += p.y;
        }
        __syncthreads();
    }

    float2* outp = g_part + ((size_t)b * NCH + c) * DIM;
#pragma unroll
    for (int h = 0; h < 4; h++) outp[t + (h << 8)] = acc[h];
}

__global__ void reduce_Fs_kernel()
{
    const int f = blockIdx.x * 256 + threadIdx.x;
    const int b = blockIdx.y;
    float2 s = make_float2(0.f, 0.f);
    const float2* p = g_part + (size_t)b * NCH * DIM + f;
    for (int c = 0; c < NCH; c++) {
        const float2 v = p[(size_t)c * DIM];
        s.x += v.x; s.y += v.y;
    }
    g_Fs[b * DIM + f] = s;
}

// ============================================================================
// output: Z = FFT(q + i*r); G = conj(Fq) - |Fr|^2; out = x + ifft(G*Fs).real
// ============================================================================
__global__ void __launch_bounds__(256) output_kernel(
    const float* __restrict__ x, float* __restrict__ out)
{
    __shared__ float2 tw[256];
    __shared__ float2 bufA[1024];
    __shared__ float2 bufB[1024];

    const int t = threadIdx.x;
    const int row = blockIdx.x;
    const int b = row >> 12;
    build_tw256(tw, t);

    const size_t base = (size_t)row * DIM;
    const float* qp = g_q + base;
    const float* rp = g_r + base;
    fft_stage1_store(
        make_float2(qp[t],       rp[t]),
        make_float2(qp[t + 256], rp[t + 256]),
        make_float2(qp[t + 512], rp[t + 512]),
        make_float2(qp[t + 768], rp[t + 768]),
        bufA, tw, t, 0);
    float2* Z = fft_tail<4>(bufA, bufB, tw, t, 0, 4);     // Z = bufA

    const float2* Fsb = g_Fs + (size_t)b * DIM;
    float2 Hreg[4];
#pragma unroll
    for (int h = 0; h < 4; h++) {
        const int f  = t + (h << 8);
        const int fn = (1024 - f) & 1023;
        const float2 z1 = Z[f];
        const float2 z2 = Z[fn];
        const float2 Fq = make_float2(0.5f * (z1.x + z2.x), 0.5f * (z1.y - z2.y));
        const float dx = z1.x - z2.x, dy = z1.y + z2.y;
        const float2 Fr = make_float2(0.5f * dy, -0.5f * dx);
        const float mag2 = fmaf(Fr.x, Fr.x, Fr.y * Fr.y);
        const float2 G = make_float2(Fq.x - mag2, -Fq.y);
        Hreg[h] = cmulf(G, Fsb[f]);
    }
    fft_stage1_store(Hreg[0], Hreg[1], Hreg[2], Hreg[3], bufB, tw, t, 1);
    float2* res = fft_tail<4>(bufB, bufA, tw, t, 1, 4);   // res = bufB

    const float* xp = x + base;
    float* op = out + base;
#pragma unroll
    for (int h = 0; h < 4; h++) {
        const int i = t + (h << 8);
        op[i] = xp[i] + res[i].x * (1.0f / 1024.0f);
    }
}

// ============================================================================
// Launch
// ============================================================================
extern "C" void kernel_launch(void* const* d_in, const int* in_sizes, int n_in,
                              void* d_out, int out_size)
{
    const float* x  = (const float*)d_in[0];
    const float* Wq = (const float*)d_in[1];
    const float* bq = (const float*)d_in[2];
    const float* Wk = (const float*)d_in[3];
    const float* bk = (const float*)d_in[4];
    const float* Wv = (const float*)d_in[5];
    const float* bv = (const float*)d_in[6];
    const float* Wr = (const float*)d_in[7];
    const float* br = (const float*)d_in[8];
    float* out = (float*)d_out;

    static bool attr_set = false;
    if (!attr_set) {
        cudaFuncSetAttribute(gemm_mma_kernel,
                             cudaFuncAttributeMaxDynamicSharedMemorySize, SMEM_DYN);
        attr_set = true;
    }

    convert_x_kernel<<<(MROWS * DIM) / 1024, 256>>>(x);
    convert_w_kernel<<<dim3((DIM * DIM) / 1024, 4), 256>>>(Wq, Wk, Wv, Wr);

    gemm_mma_kernel<<<dim3(DIM / BN, MROWS / BM, 4), 256, SMEM_DYN>>>(bq, bk, bv, br);

    bind_accum_kernel<<<dim3(NCH, BATCH), 256>>>();
    reduce_Fs_kernel<<<dim3(DIM / 256, BATCH), 256>>>();
    output_kernel<<<MROWS, 256>>>(x, out);
}

// round 9
// speedup vs baseline: 2.1296x; 1.3934x over previous
#include <cuda_runtime.h>
#include <cuda_fp16.h>
#include <math.h>
#include <stdint.h>

#define BATCH 4
#define SEQ   4096
#define DIM   1024
#define MROWS (BATCH*SEQ)       // 16384
#define NCH   256
#define CROWS (SEQ / NCH)       // 16

// ---- mma.sync GEMM tiling (single-term fp16) ----
#define BM 128
#define BN 256
#define NB_CH 16                // K chunks (1024 / 64)
#define STAGES 3
#define A_ST (BM * 128)         // 16384 B
#define B_ST (BN * 128)         // 32768 B
#define STAGE_B (A_ST + B_ST)   // 49152
#define SMEM_DYN (STAGES * STAGE_B)   // 147456

// -------- scratch (static device globals; no runtime allocation) -----------
__device__ __half g_xh[(size_t)MROWS * DIM];      // 32MB  hi only
__device__ __half g_we[4][(size_t)DIM * DIM];     // 8MB   hi only
__device__ float  g_q[(size_t)MROWS * DIM];
__device__ float  g_k[(size_t)MROWS * DIM];
__device__ float  g_v[(size_t)MROWS * DIM];
__device__ float  g_r[(size_t)MROWS * DIM];
__device__ float2 g_part[BATCH * NCH * DIM];
__device__ float2 g_Fs[BATCH * DIM];

// ============================================================================
// helpers
// ============================================================================
__device__ __forceinline__ uint32_t smem_u32(const void* p) {
    uint32_t a;
    asm("{ .reg .u64 t; cvta.to.shared.u64 t, %1; cvt.u32.u64 %0, t; }" : "=r"(a) : "l"(p));
    return a;
}

__device__ __forceinline__ void cp16(uint32_t dst, const void* src) {
    asm volatile("cp.async.cg.shared.global [%0], [%1], 16;" :: "r"(dst), "l"(src) : "memory");
}
#define CP_COMMIT() asm volatile("cp.async.commit_group;" ::: "memory")
#define CP_WAIT1()  asm volatile("cp.async.wait_group 1;" ::: "memory")

__device__ __forceinline__ void ldmx4(uint32_t& r0, uint32_t& r1, uint32_t& r2, uint32_t& r3,
                                      uint32_t addr) {
    asm volatile("ldmatrix.sync.aligned.m8n8.x4.shared.b16 {%0,%1,%2,%3}, [%4];"
                 : "=r"(r0), "=r"(r1), "=r"(r2), "=r"(r3) : "r"(addr));
}

__device__ __forceinline__ void mma16816(float* c, uint32_t a0, uint32_t a1, uint32_t a2,
                                         uint32_t a3, uint32_t b0, uint32_t b1) {
    asm volatile(
        "mma.sync.aligned.m16n8k16.row.col.f32.f16.f16.f32 "
        "{%0,%1,%2,%3}, {%4,%5,%6,%7}, {%8,%9}, {%0,%1,%2,%3};"
        : "+f"(c[0]), "+f"(c[1]), "+f"(c[2]), "+f"(c[3])
        : "r"(a0), "r"(a1), "r"(a2), "r"(a3), "r"(b0), "r"(b1));
}

__device__ __forceinline__ float tanh_fast(float x) {
    float ax = fabsf(x);
    float e = __expf(-2.0f * ax);
    float t = __fdividef(1.0f - e, 1.0f + e);
    return copysignf(t, x);
}

// swizzled smem byte offset within a (rows x 128B) tile
__device__ __forceinline__ uint32_t swz(uint32_t row, uint32_t cg) {
    return row * 128u + ((cg ^ (row & 7u)) << 4);
}

// ============================================================================
// Conversion: fp32 -> fp16 (hi only), x4 vectorized
// ============================================================================
__global__ void __launch_bounds__(256) convert_x_kernel(const float* __restrict__ x)
{
    const size_t base = ((size_t)blockIdx.x * 256 + threadIdx.x) * 4;
    const float4 v = *(const float4*)(x + base);
    __half2 h0 = make_half2(__float2half(v.x), __float2half(v.y));
    __half2 h1 = make_half2(__float2half(v.z), __float2half(v.w));
    __half2* p = (__half2*)(g_xh + base);
    p[0] = h0; p[1] = h1;
}

__global__ void __launch_bounds__(256) convert_w_kernel(
    const float* __restrict__ Wq, const float* __restrict__ Wk,
    const float* __restrict__ Wv, const float* __restrict__ Wr)
{
    const int w = blockIdx.y;
    const float* W = (w == 0) ? Wq : (w == 1) ? Wk : (w == 2) ? Wv : Wr;
    const size_t base = ((size_t)blockIdx.x * 256 + threadIdx.x) * 4;
    const float4 v = *(const float4*)(W + base);
    __half2 h0 = make_half2(__float2half(v.x), __float2half(v.y));
    __half2 h1 = make_half2(__float2half(v.z), __float2half(v.w));
    __half2* p = (__half2*)(g_we[w] + base);
    p[0] = h0; p[1] = h1;
}

// ============================================================================
// fp16 mma.sync GEMM (single term): C = tanh(Ah@Bh^T + bias)
// BM=128 x BN=256, 8 warps (warp 64x64), early prefetch + B dbl-buffer.
// ============================================================================
__global__ void __launch_bounds__(256, 1) gemm_mma_kernel(
    const float* __restrict__ bq, const float* __restrict__ bk,
    const float* __restrict__ bv, const float* __restrict__ br)
{
    extern __shared__ char dsm[];
    const uint32_t smem = smem_u32(dsm);

    const int tid = threadIdx.x, wid = tid >> 5, lane = tid & 31;
    const int nb = blockIdx.x, mb = blockIdx.y, sel = blockIdx.z;
    const int wm = wid & 1, wn = wid >> 1;       // warp tile 64(m) x 64(n)
    const float* bias = (sel == 0) ? bq : (sel == 1) ? bk : (sel == 2) ? bv : br;
    float* C = (sel == 0) ? g_q : (sel == 1) ? g_k : (sel == 2) ? g_v : g_r;

    const char* a_base = (const char*)g_xh + (size_t)mb * BM * 2048;      // 2048B/row
    const char* b_base = (const char*)g_we[sel] + (size_t)nb * BN * 2048; // 2048B/row

    const uint32_t crow0 = (uint32_t)(tid >> 3);   // 0..31
    const uint32_t ccg = (uint32_t)(tid & 7);

    float acc[4][8][4];
#pragma unroll
    for (int i = 0; i < 4; i++)
#pragma unroll
        for (int j = 0; j < 8; j++)
#pragma unroll
            for (int q = 0; q < 4; q++) acc[i][j][q] = 0.f;

    auto issue = [&](int stage, int bc) {
        const uint32_t sA = smem + stage * STAGE_B;
        const uint32_t sB = sA + A_ST;
#pragma unroll
        for (int j = 0; j < 4; j++) {
            const uint32_t r = crow0 + 32u * j;          // 0..127
            cp16(sA + swz(r, ccg), a_base + (size_t)r * 2048 + bc * 128 + ccg * 16);
        }
#pragma unroll
        for (int j = 0; j < 8; j++) {
            const uint32_t r = crow0 + 32u * j;          // 0..255
            cp16(sB + swz(r, ccg), b_base + (size_t)r * 2048 + bc * 128 + ccg * 16);
        }
    };

    issue(0, 0); CP_COMMIT();
    issue(1, 1); CP_COMMIT();

    const uint32_t a_row = (uint32_t)(wm * 64 + (lane & 15));
    const uint32_t a_kg  = (uint32_t)(lane >> 4);
    const uint32_t b_row = (uint32_t)(wn * 64 + (lane & 7) + ((lane >> 4) << 3));
    const uint32_t b_kg  = (uint32_t)((lane >> 3) & 1);

    for (int bc = 0; bc < NB_CH; bc++) {
        const int s = bc % STAGES;
        CP_WAIT1();
        __syncthreads();
        // early prefetch: the target stage was consumed last iteration
        if (bc + 2 < NB_CH) issue((bc + 2) % STAGES, bc + 2);
        CP_COMMIT();

        const uint32_t sA = smem + s * STAGE_B;
        const uint32_t sB = sA + A_ST;

        uint32_t bfr[2][4][4];           // double-buffered B fragments
#pragma unroll
        for (int nf2 = 0; nf2 < 4; nf2++)
            ldmx4(bfr[0][nf2][0], bfr[0][nf2][1], bfr[0][nf2][2], bfr[0][nf2][3],
                  sB + swz(b_row + nf2 * 16, b_kg));

#pragma unroll
        for (int ks = 0; ks < 4; ks++) {
            const int cur = ks & 1, nxt = cur ^ 1;
            uint32_t a[4][4];
#pragma unroll
            for (int mf = 0; mf < 4; mf++)
                ldmx4(a[mf][0], a[mf][1], a[mf][2], a[mf][3],
                      sA + swz(a_row + mf * 16, a_kg + ks * 2));
            // prefetch next ks B fragments
            if (ks < 3) {
#pragma unroll
                for (int nf2 = 0; nf2 < 4; nf2++)
                    ldmx4(bfr[nxt][nf2][0], bfr[nxt][nf2][1], bfr[nxt][nf2][2], bfr[nxt][nf2][3],
                          sB + swz(b_row + nf2 * 16, b_kg + (ks + 1) * 2));
            }
#pragma unroll
            for (int mf = 0; mf < 4; mf++) {
#pragma unroll
                for (int nf2 = 0; nf2 < 4; nf2++) {
                    mma16816(acc[mf][nf2 * 2 + 0], a[mf][0], a[mf][1], a[mf][2], a[mf][3],
                             bfr[cur][nf2][0], bfr[cur][nf2][1]);
                    mma16816(acc[mf][nf2 * 2 + 1], a[mf][0], a[mf][1], a[mf][2], a[mf][3],
                             bfr[cur][nf2][2], bfr[cur][nf2][3]);
                }
            }
        }
    }

    // epilogue: bias + tanh + fp32 store
#pragma unroll
    for (int mf = 0; mf < 4; mf++) {
        const int r0 = mb * BM + wm * 64 + mf * 16 + (lane >> 2);
        const int r1 = r0 + 8;
#pragma unroll
        for (int nf = 0; nf < 8; nf++) {
            const int col = nb * BN + wn * 64 + nf * 8 + (lane & 3) * 2;
            const float2 b2 = *(const float2*)(bias + col);
            float2 o0, o1;
            o0.x = tanh_fast(acc[mf][nf][0] + b2.x);
            o0.y = tanh_fast(acc[mf][nf][1] + b2.y);
            o1.x = tanh_fast(acc[mf][nf][2] + b2.x);
            o1.y = tanh_fast(acc[mf][nf][3] + b2.y);
            *(float2*)(C + (size_t)r0 * DIM + col) = o0;
            *(float2*)(C + (size_t)r1 * DIM + col) = o1;
        }
    }
}

// ============================================================================
// Radix-4 Stockham FFT, N=1024, 256 threads.
// Stage 1 (m=1) fused with data source; remaining 4 stages via fft_tail<4>.
// tw[e] = exp(-2*pi*i*e/1024), e in [0,256).
// ============================================================================
__device__ __forceinline__ float2 cmulf(float2 a, float2 b) {
    return make_float2(fmaf(a.x, b.x, -a.y * b.y), fmaf(a.x, b.y, a.y * b.x));
}
__device__ __forceinline__ float2 caddf(float2 a, float2 b) {
    return make_float2(a.x + b.x, a.y + b.y);
}
__device__ __forceinline__ float2 csubf(float2 a, float2 b) {
    return make_float2(a.x - b.x, a.y - b.y);
}

// first radix-4 stage (m=1) on 4 register inputs; float4 stores
__device__ __forceinline__ void fft_stage1_store(
    float2 x0, float2 x1, float2 x2, float2 x3,
    float2* dst, const float2* tw, int t, int inv)
{
    const float2 t0 = caddf(x0, x2);
    const float2 t1 = caddf(x1, x3);
    const float2 t2 = csubf(x0, x2);
    const float2 d  = csubf(x1, x3);
    const float2 t3 = inv ? make_float2(-d.y, d.x) : make_float2(d.y, -d.x);
    float2 w1 = tw[t];
    if (inv) w1.y = -w1.y;
    const float2 w2 = cmulf(w1, w1);
    const float2 w3 = cmulf(w2, w1);
    const float2 y0 = caddf(t0, t1);
    const float2 y1 = cmulf(w1, caddf(t2, t3));
    const float2 y2 = cmulf(w2, csubf(t0, t1));
    const float2 y3 = cmulf(w3, csubf(t2, t3));
    float4* d4 = (float4*)(dst + 4 * t);
    d4[0] = make_float4(y0.x, y0.y, y1.x, y1.y);
    d4[1] = make_float4(y2.x, y2.y, y3.x, y3.y);
}

// NS radix-4 stages starting at m = m0; returns buffer holding the result.
template <int NS>
__device__ float2* fft_tail(float2* a, float2* b, const float2* tw, int t, int inv, int m0)
{
    int m = m0;
#pragma unroll
    for (int s = 0; s < NS; s++) {
        __syncthreads();
        const int k  = t & (m - 1);
        const int jm = t - k;
        const float2 x0 = a[t];
        const float2 x1 = a[t + 256];
        const float2 x2 = a[t + 512];
        const float2 x3 = a[t + 768];
        const float2 t0 = caddf(x0, x2);
        const float2 t1 = caddf(x1, x3);
        const float2 t2 = csubf(x0, x2);
        const float2 d  = csubf(x1, x3);
        const float2 t3 = inv ? make_float2(-d.y, d.x) : make_float2(d.y, -d.x);
        float2 w1 = tw[jm];
        if (inv) w1.y = -w1.y;
        const float2 w2 = cmulf(w1, w1);
        const float2 w3 = cmulf(w2, w1);
        const int o = 4 * jm + k;
        b[o]         = caddf(t0, t1);
        b[o + m]     = cmulf(w1, caddf(t2, t3));
        b[o + 2 * m] = cmulf(w2, csubf(t0, t1));
        b[o + 3 * m] = cmulf(w3, csubf(t2, t3));
        float2* tmp = a; a = b; b = tmp;
        m <<= 2;
    }
    __syncthreads();
    return a;
}

__device__ __forceinline__ void build_tw256(float2* tw, int t)
{
    float sn, cs;
    sincosf(-2.0f * (float)M_PI * (float)t * (1.0f / 1024.0f), &sn, &cs);
    tw[t] = make_float2(cs, sn);
}

// ============================================================================
// bind + accumulate: Z = FFT(k + i*v); acc += Fk*Fv (Hermitian extraction)
// ============================================================================
__global__ void __launch_bounds__(256) bind_accum_kernel()
{
    __shared__ float2 tw[256];
    __shared__ float2 bufA[1024];
    __shared__ float2 bufB[1024];

    const int t = threadIdx.x;
    const int c = blockIdx.x;
    const int b = blockIdx.y;
    build_tw256(tw, t);

    float2 acc[4];
#pragma unroll
    for (int h = 0; h < 4; h++) acc[h] = make_float2(0.f, 0.f);

    const size_t base = ((size_t)b * SEQ + (size_t)c * CROWS) * DIM;
    for (int r = 0; r < CROWS; r++) {
        const float* kp = g_k + base + (size_t)r * DIM;
        const float* vp = g_v + base + (size_t)r * DIM;
        fft_stage1_store(
            make_float2(kp[t],       vp[t]),
            make_float2(kp[t + 256], vp[t + 256]),
            make_float2(kp[t + 512], vp[t + 512]),
            make_float2(kp[t + 768], vp[t + 768]),
            bufA, tw, t, 0);
        float2* Z = fft_tail<4>(bufA, bufB, tw, t, 0, 4);   // Z = bufA
#pragma unroll
        for (int h = 0; h < 4; h++) {
            const int f  = t + (h << 8);
            const int fn = (1024 - f) & 1023;
            const float2 z1 = Z[f];
            const float2 z2 = Z[fn];
            const float2 Fk = make_float2(0.5f * (z1.x + z2.x), 0.5f * (z1.y - z2.y));
            const float dx = z1.x - z2.x, dy = z1.y + z2.y;
            const float2 Fv = make_float2(0.5f * dy, -0.5f * dx);
            const float2 p = cmulf(Fk, Fv);
            acc[h].x += p.x; acc[h].y += p.y;
        }
        __syncthreads();
    }

    float2* outp = g_part + ((size_t)b * NCH + c) * DIM;
#pragma unroll
    for (int h = 0; h < 4; h++) outp[t + (h << 8)] = acc[h];
}

__global__ void reduce_Fs_kernel()
{
    const int f = blockIdx.x * 256 + threadIdx.x;
    const int b = blockIdx.y;
    float2 s = make_float2(0.f, 0.f);
    const float2* p = g_part + (size_t)b * NCH * DIM + f;
    for (int c = 0; c < NCH; c++) {
        const float2 v = p[(size_t)c * DIM];
        s.x += v.x; s.y += v.y;
    }
    g_Fs[b * DIM + f] = s;
}

// ============================================================================
// output: Z = FFT(q + i*r); G = conj(Fq) - |Fr|^2; out = x + ifft(G*Fs).real
// ============================================================================
__global__ void __launch_bounds__(256) output_kernel(
    const float* __restrict__ x, float* __restrict__ out)
{
    __shared__ float2 tw[256];
    __shared__ float2 bufA[1024];
    __shared__ float2 bufB[1024];

    const int t = threadIdx.x;
    const int row = blockIdx.x;
    const int b = row >> 12;
    build_tw256(tw, t);

    const size_t base = (size_t)row * DIM;
    const float* qp = g_q + base;
    const float* rp = g_r + base;
    fft_stage1_store(
        make_float2(qp[t],       rp[t]),
        make_float2(qp[t + 256], rp[t + 256]),
        make_float2(qp[t + 512], rp[t + 512]),
        make_float2(qp[t + 768], rp[t + 768]),
        bufA, tw, t, 0);
    float2* Z = fft_tail<4>(bufA, bufB, tw, t, 0, 4);     // Z = bufA

    const float2* Fsb = g_Fs + (size_t)b * DIM;
    float2 Hreg[4];
#pragma unroll
    for (int h = 0; h < 4; h++) {
        const int f  = t + (h << 8);
        const int fn = (1024 - f) & 1023;
        const float2 z1 = Z[f];
        const float2 z2 = Z[fn];
        const float2 Fq = make_float2(0.5f * (z1.x + z2.x), 0.5f * (z1.y - z2.y));
        const float dx = z1.x - z2.x, dy = z1.y + z2.y;
        const float2 Fr = make_float2(0.5f * dy, -0.5f * dx);
        const float mag2 = fmaf(Fr.x, Fr.x, Fr.y * Fr.y);
        const float2 G = make_float2(Fq.x - mag2, -Fq.y);
        Hreg[h] = cmulf(G, Fsb[f]);
    }
    fft_stage1_store(Hreg[0], Hreg[1], Hreg[2], Hreg[3], bufB, tw, t, 1);
    float2* res = fft_tail<4>(bufB, bufA, tw, t, 1, 4);   // res = bufB

    const float* xp = x + base;
    float* op = out + base;
#pragma unroll
    for (int h = 0; h < 4; h++) {
        const int i = t + (h << 8);
        op[i] = xp[i] + res[i].x * (1.0f / 1024.0f);
    }
}

// ============================================================================
// Launch
// ============================================================================
extern "C" void kernel_launch(void* const* d_in, const int* in_sizes, int n_in,
                              void* d_out, int out_size)
{
    const float* x  = (const float*)d_in[0];
    const float* Wq = (const float*)d_in[1];
    const float* bq = (const float*)d_in[2];
    const float* Wk = (const float*)d_in[3];
    const float* bk = (const float*)d_in[4];
    const float* Wv = (const float*)d_in[5];
    const float* bv = (const float*)d_in[6];
    const float* Wr = (const float*)d_in[7];
    const float* br = (const float*)d_in[8];
    float* out = (float*)d_out;

    static bool attr_set = false;
    if (!attr_set) {
        cudaFuncSetAttribute(gemm_mma_kernel,
                             cudaFuncAttributeMaxDynamicSharedMemorySize, SMEM_DYN);
        attr_set = true;
    }

    convert_x_kernel<<<(MROWS * DIM) / 1024, 256>>>(x);
    convert_w_kernel<<<dim3((DIM * DIM) / 1024, 4), 256>>>(Wq, Wk, Wv, Wr);

    gemm_mma_kernel<<<dim3(DIM / BN, MROWS / BM, 4), 256, SMEM_DYN>>>(bq, bk, bv, br);

    bind_accum_kernel<<<dim3(NCH, BATCH), 256>>>();
    reduce_Fs_kernel<<<dim3(DIM / 256, BATCH), 256>>>();
    output_kernel<<<MROWS, 256>>>(x, out);
}